// round 4
// baseline (speedup 1.0000x reference)
#include <cuda_runtime.h>
#include <math.h>

// Problem constants
#define BATCH 2
#define T_SEQ 2048
#define HID   2048
#define NHEAD 16
#define HDIM  128
#define MROWS (BATCH * T_SEQ)   // 4096

// Scratch (device globals; allocation-free kernel_launch)
__device__ float g_q[BATCH * NHEAD * T_SEQ * HDIM];   // [b,h,t,d]
__device__ float g_k[BATCH * NHEAD * T_SEQ * HDIM];
__device__ float g_v[BATCH * NHEAD * T_SEQ * HDIM];
__device__ float g_ao[MROWS * HID];                   // [b*t, h*d]

// ---------------------------------------------------------------------------
// Fused QKV SGEMM: for z = blockIdx.z in {0,1,2}:
//   C_z[b,h,t,d] = x[m,:] . W_z[n,:]   (m = b*2048+t, n = h*128+d)
// z=0 (Q) and z=1 (K) additionally apply RoPE in the epilogue.
// 128x128 block tile, BK=16, 256 threads, 8x8 per thread (two 4x4 quadrants;
// quadrant 0 = cols d in [0,64), quadrant 1 = cols d+64 -> rotate-half pairs).
// ---------------------------------------------------------------------------
__global__ __launch_bounds__(256, 2)
void qkv_gemm_kernel(const float* __restrict__ A,
                     const float* __restrict__ Wq, const float* __restrict__ Wk,
                     const float* __restrict__ Wv,
                     float* __restrict__ Cq, float* __restrict__ Ck,
                     float* __restrict__ Cv,
                     const float* __restrict__ cosb, const float* __restrict__ sinb)
{
    __shared__ float As[16][132];   // [k][m], padded stride
    __shared__ float Ws[16][132];   // [k][n]
    const int K = HID;
    int z = blockIdx.z;
    const float* W = (z == 0) ? Wq : (z == 1) ? Wk : Wv;
    float* C = (z == 0) ? Cq : (z == 1) ? Ck : Cv;
    bool do_rope = (z < 2);

    int tid = threadIdx.x;
    int tx = tid & 15, ty = tid >> 4;
    int n0 = blockIdx.x * 128;
    int m0 = blockIdx.y * 128;

    float4 pa[2], pw[2];
#pragma unroll
    for (int i = 0; i < 2; i++) {
        int idx = tid + i * 256;
        int row = idx >> 2, kq = idx & 3;
        pa[i] = *(const float4*)&A[(m0 + row) * K + kq * 4];
        pw[i] = *(const float4*)&W[(n0 + row) * K + kq * 4];
    }

    float acc[8][8];
#pragma unroll
    for (int i = 0; i < 8; i++)
#pragma unroll
        for (int j = 0; j < 8; j++) acc[i][j] = 0.f;

    for (int k0 = 0; k0 < K; k0 += 16) {
#pragma unroll
        for (int i = 0; i < 2; i++) {
            int idx = tid + i * 256;
            int row = idx >> 2, kq = idx & 3;
            As[kq * 4 + 0][row] = pa[i].x;
            As[kq * 4 + 1][row] = pa[i].y;
            As[kq * 4 + 2][row] = pa[i].z;
            As[kq * 4 + 3][row] = pa[i].w;
            Ws[kq * 4 + 0][row] = pw[i].x;
            Ws[kq * 4 + 1][row] = pw[i].y;
            Ws[kq * 4 + 2][row] = pw[i].z;
            Ws[kq * 4 + 3][row] = pw[i].w;
        }
        __syncthreads();
        int kn = k0 + 16;
        if (kn < K) {
#pragma unroll
            for (int i = 0; i < 2; i++) {
                int idx = tid + i * 256;
                int row = idx >> 2, kq = idx & 3;
                pa[i] = *(const float4*)&A[(m0 + row) * K + kn + kq * 4];
                pw[i] = *(const float4*)&W[(n0 + row) * K + kn + kq * 4];
            }
        }
#pragma unroll
        for (int kk = 0; kk < 16; kk++) {
            float a[8], b[8];
            *(float4*)&a[0] = *(const float4*)&As[kk][ty * 4];
            *(float4*)&a[4] = *(const float4*)&As[kk][64 + ty * 4];
            *(float4*)&b[0] = *(const float4*)&Ws[kk][tx * 4];
            *(float4*)&b[4] = *(const float4*)&Ws[kk][64 + tx * 4];
#pragma unroll
            for (int i = 0; i < 8; i++)
#pragma unroll
                for (int j = 0; j < 8; j++) acc[i][j] += a[i] * b[j];
        }
        __syncthreads();
    }

    // Epilogue: scatter to [b,h,t,d]; RoPE for Q/K.
    // Thread's cols: quadrant 0 -> d = tx*4+j (in [0,64)); quadrant 1 -> d+64.
    int h = n0 >> 7;
#pragma unroll
    for (int i = 0; i < 8; i++) {
        int rl = (i < 4) ? (ty * 4 + i) : (64 + ty * 4 + i - 4);
        int rm = m0 + rl;
        int b = rm >> 11, t = rm & 2047;
        float lo[4], hi[4];
#pragma unroll
        for (int j = 0; j < 4; j++) { lo[j] = acc[i][j]; hi[j] = acc[i][4 + j]; }
        if (do_rope) {
#pragma unroll
            for (int j = 0; j < 4; j++) {
                int d = tx * 4 + j;
                float c0 = cosb[t * HDIM + d],      s0 = sinb[t * HDIM + d];
                float c1 = cosb[t * HDIM + 64 + d], s1 = sinb[t * HDIM + 64 + d];
                float a = lo[j], bb = hi[j];
                lo[j] = a * c0 - bb * s0;
                hi[j] = bb * c1 + a * s1;
            }
        }
        int base = ((b * NHEAD + h) * T_SEQ + t) * HDIM;
        *(float4*)&C[base + tx * 4]      = make_float4(lo[0], lo[1], lo[2], lo[3]);
        *(float4*)&C[base + 64 + tx * 4] = make_float4(hi[0], hi[1], hi[2], hi[3]);
    }
}

// ---------------------------------------------------------------------------
// Output-projection SGEMM: C[M,N] = A[M,K] * W[N,K]^T, row-major C.
// ---------------------------------------------------------------------------
__global__ __launch_bounds__(256, 2)
void sgemm_kernel(const float* __restrict__ A, const float* __restrict__ W,
                  float* __restrict__ C)
{
    __shared__ float As[16][132];
    __shared__ float Ws[16][132];
    const int K = HID, N = HID;
    int tid = threadIdx.x;
    int tx = tid & 15, ty = tid >> 4;
    int n0 = blockIdx.x * 128;
    int m0 = blockIdx.y * 128;

    float4 pa[2], pw[2];
#pragma unroll
    for (int i = 0; i < 2; i++) {
        int idx = tid + i * 256;
        int row = idx >> 2, kq = idx & 3;
        pa[i] = *(const float4*)&A[(m0 + row) * K + kq * 4];
        pw[i] = *(const float4*)&W[(n0 + row) * K + kq * 4];
    }

    float acc[8][8];
#pragma unroll
    for (int i = 0; i < 8; i++)
#pragma unroll
        for (int j = 0; j < 8; j++) acc[i][j] = 0.f;

    for (int k0 = 0; k0 < K; k0 += 16) {
#pragma unroll
        for (int i = 0; i < 2; i++) {
            int idx = tid + i * 256;
            int row = idx >> 2, kq = idx & 3;
            As[kq * 4 + 0][row] = pa[i].x;
            As[kq * 4 + 1][row] = pa[i].y;
            As[kq * 4 + 2][row] = pa[i].z;
            As[kq * 4 + 3][row] = pa[i].w;
            Ws[kq * 4 + 0][row] = pw[i].x;
            Ws[kq * 4 + 1][row] = pw[i].y;
            Ws[kq * 4 + 2][row] = pw[i].z;
            Ws[kq * 4 + 3][row] = pw[i].w;
        }
        __syncthreads();
        int kn = k0 + 16;
        if (kn < K) {
#pragma unroll
            for (int i = 0; i < 2; i++) {
                int idx = tid + i * 256;
                int row = idx >> 2, kq = idx & 3;
                pa[i] = *(const float4*)&A[(m0 + row) * K + kn + kq * 4];
                pw[i] = *(const float4*)&W[(n0 + row) * K + kn + kq * 4];
            }
        }
#pragma unroll
        for (int kk = 0; kk < 16; kk++) {
            float a[8], b[8];
            *(float4*)&a[0] = *(const float4*)&As[kk][ty * 4];
            *(float4*)&a[4] = *(const float4*)&As[kk][64 + ty * 4];
            *(float4*)&b[0] = *(const float4*)&Ws[kk][tx * 4];
            *(float4*)&b[4] = *(const float4*)&Ws[kk][64 + tx * 4];
#pragma unroll
            for (int i = 0; i < 8; i++)
#pragma unroll
                for (int j = 0; j < 8; j++) acc[i][j] += a[i] * b[j];
        }
        __syncthreads();
    }

#pragma unroll
    for (int i = 0; i < 8; i++) {
        int rl = (i < 4) ? (ty * 4 + i) : (64 + ty * 4 + i - 4);
        int rm = m0 + rl;
        *(float4*)&C[rm * N + n0 + tx * 4]      = make_float4(acc[i][0], acc[i][1], acc[i][2], acc[i][3]);
        *(float4*)&C[rm * N + n0 + 64 + tx * 4] = make_float4(acc[i][4], acc[i][5], acc[i][6], acc[i][7]);
    }
}

// ---------------------------------------------------------------------------
// Flash attention (fp32), causal. Br=Bc=64, D=128. 256 threads (8 warps).
// Warp w owns rows w*8..w*8+7. Lane owns score cols {lane, lane+32} and
// output dims {4*lane..4*lane+3}. Online softmax kept in registers.
// Output to g_ao [b, t, h*128+d].
// ---------------------------------------------------------------------------
#define FL_SMEM_FLOATS (64*128 + 64*132 + 64*132 + 64*64)

__global__ __launch_bounds__(256, 1)
void flash_kernel(const float* __restrict__ Qg, const float* __restrict__ Kg,
                  const float* __restrict__ Vg, float* __restrict__ Og)
{
    extern __shared__ float sm[];
    float* Qs = sm;                    // [64][128]
    float* Ks = Qs + 64 * 128;         // [64][132]
    float* Vs = Ks + 64 * 132;         // [64][132]
    float* Ps = Vs + 64 * 132;         // [64][64]

    int tid = threadIdx.x, lane = tid & 31, w = tid >> 5;
    int bh = blockIdx.y;
    int qi = gridDim.x - 1 - blockIdx.x;   // heavy tiles scheduled first
    int row0 = qi * 64;

    const float* Qb = Qg + (size_t)bh * T_SEQ * HDIM;
    const float* Kb = Kg + (size_t)bh * T_SEQ * HDIM;
    const float* Vb = Vg + (size_t)bh * T_SEQ * HDIM;

    // stage Q tile (64x128)
#pragma unroll
    for (int i = 0; i < 8; i++) {
        int e = tid + i * 256;
        int r = e >> 5, c4 = e & 31;
        *(float4*)&Qs[r * 128 + c4 * 4] = *(const float4*)&Qb[(row0 + r) * HDIM + c4 * 4];
    }

    float o[8][4];
    float mrow[8], lrow[8];
#pragma unroll
    for (int r = 0; r < 8; r++) {
        mrow[r] = -1e30f; lrow[r] = 0.f;
        o[r][0] = o[r][1] = o[r][2] = o[r][3] = 0.f;
    }
    const float scale = 0.08838834764831845f;   // 1/sqrt(128)

    for (int j = 0; j <= qi; j++) {
        __syncthreads();
#pragma unroll
        for (int i = 0; i < 8; i++) {
            int e = tid + i * 256;
            int r = e >> 5, c4 = e & 31;
            *(float4*)&Ks[r * 132 + c4 * 4] = *(const float4*)&Kb[(j * 64 + r) * HDIM + c4 * 4];
            *(float4*)&Vs[r * 132 + c4 * 4] = *(const float4*)&Vb[(j * 64 + r) * HDIM + c4 * 4];
        }
        __syncthreads();

        // S = Q * K^T for this warp's 8 rows x 64 cols
        float s0[8], s1[8];
#pragma unroll
        for (int r = 0; r < 8; r++) { s0[r] = 0.f; s1[r] = 0.f; }
        for (int k4 = 0; k4 < 128; k4 += 4) {
            float4 kv0 = *(const float4*)&Ks[lane * 132 + k4];
            float4 kv1 = *(const float4*)&Ks[(lane + 32) * 132 + k4];
#pragma unroll
            for (int r = 0; r < 8; r++) {
                float4 qv = *(const float4*)&Qs[(w * 8 + r) * 128 + k4];
                s0[r] += qv.x * kv0.x + qv.y * kv0.y + qv.z * kv0.z + qv.w * kv0.w;
                s1[r] += qv.x * kv1.x + qv.y * kv1.y + qv.z * kv1.z + qv.w * kv1.w;
            }
        }

        bool diag = (j == qi);
#pragma unroll
        for (int r = 0; r < 8; r++) {
            float v0 = s0[r] * scale, v1 = s1[r] * scale;
            if (diag) {
                int gi = w * 8 + r;            // local row == global offset on diagonal tile
                if (lane > gi)      v0 = -1e30f;
                if (lane + 32 > gi) v1 = -1e30f;
            }
            float mx = fmaxf(v0, v1);
#pragma unroll
            for (int off = 16; off > 0; off >>= 1)
                mx = fmaxf(mx, __shfl_xor_sync(0xffffffffu, mx, off));
            float mnew = fmaxf(mrow[r], mx);
            float corr = __expf(mrow[r] - mnew);
            float p0 = __expf(v0 - mnew);
            float p1 = __expf(v1 - mnew);
            float sum = p0 + p1;
#pragma unroll
            for (int off = 16; off > 0; off >>= 1)
                sum += __shfl_xor_sync(0xffffffffu, sum, off);
            lrow[r] = lrow[r] * corr + sum;
            mrow[r] = mnew;
            o[r][0] *= corr; o[r][1] *= corr; o[r][2] *= corr; o[r][3] *= corr;
            Ps[(w * 8 + r) * 64 + lane]      = p0;
            Ps[(w * 8 + r) * 64 + lane + 32] = p1;
        }
        __syncwarp();

        // O += P * V
        for (int c4 = 0; c4 < 64; c4 += 4) {
            float4 va = *(const float4*)&Vs[(c4 + 0) * 132 + lane * 4];
            float4 vb = *(const float4*)&Vs[(c4 + 1) * 132 + lane * 4];
            float4 vc = *(const float4*)&Vs[(c4 + 2) * 132 + lane * 4];
            float4 vd = *(const float4*)&Vs[(c4 + 3) * 132 + lane * 4];
#pragma unroll
            for (int r = 0; r < 8; r++) {
                float4 p = *(const float4*)&Ps[(w * 8 + r) * 64 + c4];
                o[r][0] += p.x * va.x + p.y * vb.x + p.z * vc.x + p.w * vd.x;
                o[r][1] += p.x * va.y + p.y * vb.y + p.z * vc.y + p.w * vd.y;
                o[r][2] += p.x * va.z + p.y * vb.z + p.z * vc.z + p.w * vd.z;
                o[r][3] += p.x * va.w + p.y * vb.w + p.z * vc.w + p.w * vd.w;
            }
        }
        __syncwarp();
    }

    // epilogue: normalize + write [b, t, h*128 + d]
    int b = bh >> 4, h = bh & 15;
#pragma unroll
    for (int r = 0; r < 8; r++) {
        float inv = 1.f / lrow[r];
        int t = row0 + w * 8 + r;
        float4 val = make_float4(o[r][0] * inv, o[r][1] * inv, o[r][2] * inv, o[r][3] * inv);
        *(float4*)&Og[(size_t)(b * T_SEQ + t) * HID + h * HDIM + lane * 4] = val;
    }
}

// ---------------------------------------------------------------------------
extern "C" void kernel_launch(void* const* d_in, const int* in_sizes, int n_in,
                              void* d_out, int out_size)
{
    const float* x    = (const float*)d_in[0];
    const float* cosb = (const float*)d_in[1];
    const float* sinb = (const float*)d_in[2];
    const float* Wq   = (const float*)d_in[3];
    const float* Wk   = (const float*)d_in[4];
    const float* Wv   = (const float*)d_in[5];
    const float* Wo   = (const float*)d_in[6];
    float* out = (float*)d_out;

    float *q, *k, *v, *ao;
    cudaGetSymbolAddress((void**)&q,  g_q);
    cudaGetSymbolAddress((void**)&k,  g_k);
    cudaGetSymbolAddress((void**)&v,  g_v);
    cudaGetSymbolAddress((void**)&ao, g_ao);

    // Fused QKV projection + RoPE (z: 0=Q,1=K,2=V)
    dim3 gqkv(HID / 128, MROWS / 128, 3);   // (16, 32, 3)
    qkv_gemm_kernel<<<gqkv, 256>>>(x, Wq, Wk, Wv, q, k, v, cosb, sinb);

    const int FLASH_SMEM = FL_SMEM_FLOATS * (int)sizeof(float);   // 116736 B
    cudaFuncSetAttribute(flash_kernel, cudaFuncAttributeMaxDynamicSharedMemorySize, FLASH_SMEM);
    flash_kernel<<<dim3(T_SEQ / 64, BATCH * NHEAD), 256, FLASH_SMEM>>>(q, k, v, ao);

    sgemm_kernel<<<dim3(HID / 128, MROWS / 128), 256>>>(ao, Wo, out);
}

// round 7
// speedup vs baseline: 1.4823x; 1.4823x over previous
#include <cuda_runtime.h>
#include <cuda_bf16.h>
#include <cstdint>
#include <math.h>

// Problem constants
#define BATCH 2
#define T_SEQ 2048
#define HID   2048
#define NHEAD 16
#define HDIM  128
#define MROWS (BATCH * T_SEQ)   // 4096
#define KDIM  2048

// ---------------------------------------------------------------------------
// Scratch (device globals; allocation-free kernel_launch)
// ---------------------------------------------------------------------------
__device__ float g_q[BATCH * NHEAD * T_SEQ * HDIM];   // [b,h,t,d]
__device__ float g_k[BATCH * NHEAD * T_SEQ * HDIM];
__device__ float g_v[BATCH * NHEAD * T_SEQ * HDIM];
__device__ float g_ao[MROWS * HID];                   // [b*t, h*d]

__device__ __nv_bfloat16 g_xhi[MROWS * KDIM];         // split activations
__device__ __nv_bfloat16 g_xlo[MROWS * KDIM];
__device__ __nv_bfloat16 g_whi[4 * HID * KDIM];       // split weights: Wq,Wk,Wv,Wo
__device__ __nv_bfloat16 g_wlo[4 * HID * KDIM];

// ---------------------------------------------------------------------------
// PTX helpers (baseline PTX only: ldmatrix / mma.sync / cp.async — no tcgen05)
// ---------------------------------------------------------------------------
__device__ __forceinline__ uint32_t smem_u32(const void* p) {
    uint32_t a;
    asm("{ .reg .u64 t; cvta.to.shared.u64 t, %1; cvt.u32.u64 %0, t; }" : "=r"(a) : "l"(p));
    return a;
}

#define LDM4(r, addr) \
    asm volatile("ldmatrix.sync.aligned.m8n8.x4.shared.b16 {%0,%1,%2,%3}, [%4];" \
        : "=r"((r)[0]), "=r"((r)[1]), "=r"((r)[2]), "=r"((r)[3]) : "r"(addr))

#define MMA_BF16(d, a, b0, b1) \
    asm volatile("mma.sync.aligned.m16n8k16.row.col.f32.bf16.bf16.f32 " \
        "{%0,%1,%2,%3}, {%4,%5,%6,%7}, {%8,%9}, {%0,%1,%2,%3};" \
        : "+f"((d)[0]), "+f"((d)[1]), "+f"((d)[2]), "+f"((d)[3]) \
        : "r"((a)[0]), "r"((a)[1]), "r"((a)[2]), "r"((a)[3]), "r"(b0), "r"(b1))

#define CP16(s, g) \
    asm volatile("cp.async.cg.shared.global [%0], [%1], 16;" \
        :: "r"(s), "l"(__cvta_generic_to_global(g)) : "memory")
#define CP_COMMIT() asm volatile("cp.async.commit_group;" ::: "memory")
#define CP_WAIT1()  asm volatile("cp.async.wait_group 1;" ::: "memory")
#define CP_WAIT0()  asm volatile("cp.async.wait_group 0;" ::: "memory")

// ---------------------------------------------------------------------------
// fp32 -> (bf16 hi, bf16 lo) split, 4 elems/thread
// ---------------------------------------------------------------------------
struct alignas(8) bf16x4 { __nv_bfloat162 a, b; };

__global__ void split_kernel(const float* __restrict__ src,
                             __nv_bfloat16* __restrict__ hi,
                             __nv_bfloat16* __restrict__ lo, int n4)
{
    int i = blockIdx.x * blockDim.x + threadIdx.x;
    if (i >= n4) return;
    float4 v = ((const float4*)src)[i];
    __nv_bfloat16 h0 = __float2bfloat16(v.x);
    __nv_bfloat16 h1 = __float2bfloat16(v.y);
    __nv_bfloat16 h2 = __float2bfloat16(v.z);
    __nv_bfloat16 h3 = __float2bfloat16(v.w);
    __nv_bfloat16 l0 = __float2bfloat16(v.x - __bfloat162float(h0));
    __nv_bfloat16 l1 = __float2bfloat16(v.y - __bfloat162float(h1));
    __nv_bfloat16 l2 = __float2bfloat16(v.z - __bfloat162float(h2));
    __nv_bfloat16 l3 = __float2bfloat16(v.w - __bfloat162float(h3));
    bf16x4 hv, lv;
    hv.a = __nv_bfloat162(h0, h1); hv.b = __nv_bfloat162(h2, h3);
    lv.a = __nv_bfloat162(l0, l1); lv.b = __nv_bfloat162(l2, l3);
    ((bf16x4*)hi)[i] = hv;
    ((bf16x4*)lo)[i] = lv;
}

// ---------------------------------------------------------------------------
// mma.sync split-bf16 GEMM tile: C[128,128] = A[128,K] * B[128,K]^T (fp32 acc).
// 8 warps = 2(M) x 4(N); warp tile 64x32 = 4x4 m16n8k16 atoms; BK=32.
// smem: 2 stages x 4 tiles (Ahi, Alo, Bhi, Blo), each 128 rows x 40 bf16
// (stride 40 elems = 80 B: conflict-free ldmatrix, row bank pattern
//  {0,20,8,28,16,4,24,12}). cp.async 2-stage pipeline.
// Result lands in acc[4][4][4]; caller stages into smem for its epilogue.
// ---------------------------------------------------------------------------
#define TILE_B   10240            // 128 * 40 * 2
#define STAGE_B  (4 * TILE_B)     // 40960
#define GEMM_SMEM (2 * STAGE_B)   // 81920

__device__ __forceinline__ void mma_gemm_tile(
    const __nv_bfloat16* __restrict__ Ah, const __nv_bfloat16* __restrict__ Al,
    const __nv_bfloat16* __restrict__ Bh, const __nv_bfloat16* __restrict__ Bl,
    uint32_t sbase, float acc[4][4][4])
{
    int tid = threadIdx.x, lane = tid & 31, w = tid >> 5;
    int wm = w & 1, wn = w >> 1;
    uint32_t r8 = lane & 7, mi = lane >> 3;
    // ldmatrix x4 per-lane row addresses (byte offsets within a tile)
    uint32_t a_off = ((wm * 64 + ((mi & 1) << 3) + r8) * 40 + ((mi >> 1) << 3)) * 2;
    uint32_t b_off = ((wn * 32 + ((mi >> 1) << 3) + r8) * 40 + ((mi & 1) << 3)) * 2;

    // per-thread cp.async slots: 2 x (row, kq)
    int e0 = tid, e1 = tid + 256;
    int r0 = e0 >> 2, kq0 = e0 & 3;
    int r1 = e1 >> 2, kq1 = e1 & 3;
    uint32_t so0 = (uint32_t)((r0 * 40 + kq0 * 8) * 2);
    uint32_t so1 = (uint32_t)((r1 * 40 + kq1 * 8) * 2);

    auto issue = [&](int c, int buf) {
        uint32_t sb = sbase + buf * STAGE_B;
        size_t g0 = (size_t)r0 * KDIM + c * 32 + kq0 * 8;
        size_t g1 = (size_t)r1 * KDIM + c * 32 + kq1 * 8;
        CP16(sb + 0 * TILE_B + so0, Ah + g0);
        CP16(sb + 0 * TILE_B + so1, Ah + g1);
        CP16(sb + 1 * TILE_B + so0, Al + g0);
        CP16(sb + 1 * TILE_B + so1, Al + g1);
        CP16(sb + 2 * TILE_B + so0, Bh + g0);
        CP16(sb + 2 * TILE_B + so1, Bh + g1);
        CP16(sb + 3 * TILE_B + so0, Bl + g0);
        CP16(sb + 3 * TILE_B + so1, Bl + g1);
    };

    auto compute = [&](int buf) {
        uint32_t sb = sbase + buf * STAGE_B;
#pragma unroll
        for (int ks = 0; ks < 2; ks++) {
            uint32_t k0b = ks * 32;   // 16 bf16 = 32 B
            uint32_t bh[8], bl[8];
#pragma unroll
            for (int p = 0; p < 2; p++) {
                LDM4(&bh[p * 4], sb + 2 * TILE_B + b_off + p * 1280 + k0b);
                LDM4(&bl[p * 4], sb + 3 * TILE_B + b_off + p * 1280 + k0b);
            }
#pragma unroll
            for (int ma = 0; ma < 4; ma++) {
                uint32_t ah[4], al[4];
                LDM4(ah, sb + 0 * TILE_B + a_off + ma * 1280 + k0b);
                LDM4(al, sb + 1 * TILE_B + a_off + ma * 1280 + k0b);
#pragma unroll
                for (int na = 0; na < 4; na++) {
                    int bi = (na >> 1) * 4 + (na & 1) * 2;
                    MMA_BF16(acc[ma][na], ah, bh[bi], bh[bi + 1]);
                    MMA_BF16(acc[ma][na], ah, bl[bi], bl[bi + 1]);
                    MMA_BF16(acc[ma][na], al, bh[bi], bh[bi + 1]);
                }
            }
        }
    };

    const int NCH = KDIM / 32;   // 64
    issue(0, 0); CP_COMMIT();
    for (int c = 0; c < NCH; c++) {
        if (c + 1 < NCH) { issue(c + 1, (c + 1) & 1); CP_COMMIT(); CP_WAIT1(); }
        else             { CP_WAIT0(); }
        __syncthreads();
        compute(c & 1);
        __syncthreads();
    }
}

// stage acc -> smem float[128][132]
__device__ __forceinline__ void acc_to_smem(float* Cs, float acc[4][4][4])
{
    int tid = threadIdx.x, lane = tid & 31, w = tid >> 5;
    int wm = w & 1, wn = w >> 1;
    int g = lane >> 2, tg = lane & 3;
#pragma unroll
    for (int ma = 0; ma < 4; ma++)
#pragma unroll
        for (int na = 0; na < 4; na++) {
            int col = wn * 32 + na * 8 + tg * 2;
            int row = wm * 64 + ma * 16 + g;
            *(float2*)&Cs[row * 132 + col]       = make_float2(acc[ma][na][0], acc[ma][na][1]);
            *(float2*)&Cs[(row + 8) * 132 + col] = make_float2(acc[ma][na][2], acc[ma][na][3]);
        }
}

// ---------------------------------------------------------------------------
// QKV projection (+RoPE) on mma.sync tensor cores.
// grid (16, 32, 3): n-block = head (128 cols), m-block = 128 tokens, z = Q/K/V.
// ---------------------------------------------------------------------------
__global__ __launch_bounds__(256, 1)
void qkv_mma_kernel(const __nv_bfloat16* __restrict__ xhi, const __nv_bfloat16* __restrict__ xlo,
                    const __nv_bfloat16* __restrict__ whi, const __nv_bfloat16* __restrict__ wlo,
                    float* __restrict__ q, float* __restrict__ k, float* __restrict__ v,
                    const float* __restrict__ cosb, const float* __restrict__ sinb)
{
    extern __shared__ char smem[];
    uint32_t sbase = smem_u32(smem);
    int tid = threadIdx.x;
    int z = blockIdx.z;
    int n0 = blockIdx.x * 128, m0 = blockIdx.y * 128;
    int h = n0 >> 7;

    const __nv_bfloat16* Ah = xhi + (size_t)m0 * KDIM;
    const __nv_bfloat16* Al = xlo + (size_t)m0 * KDIM;
    const __nv_bfloat16* Bh = whi + (size_t)z * HID * KDIM + (size_t)n0 * KDIM;
    const __nv_bfloat16* Bl = wlo + (size_t)z * HID * KDIM + (size_t)n0 * KDIM;
    float* C = (z == 0) ? q : (z == 1) ? k : v;

    float acc[4][4][4];
#pragma unroll
    for (int i = 0; i < 4; i++)
#pragma unroll
        for (int j = 0; j < 4; j++)
#pragma unroll
            for (int c = 0; c < 4; c++) acc[i][j][c] = 0.f;

    mma_gemm_tile(Ah, Al, Bh, Bl, sbase, acc);

    float* Cs = (float*)smem;
    acc_to_smem(Cs, acc);
    __syncthreads();

    // epilogue: RoPE (for Q/K) + scatter to [b,h,t,d]
    bool rope = (z < 2);
    int r = tid >> 1, half = tid & 1;
    int m = m0 + r;
    int b = m >> 11, t = m & 2047;
    float* outp = C + ((size_t)((b * NHEAD + h) * T_SEQ + t)) * HDIM;
    int d0 = half * 32;
#pragma unroll
    for (int j = 0; j < 32; j += 4) {
        int d = d0 + j;
        float4 lo = *(float4*)&Cs[r * 132 + d];
        float4 hi = *(float4*)&Cs[r * 132 + d + 64];
        if (rope) {
            float4 c0 = *(const float4*)&cosb[t * HDIM + d];
            float4 s0 = *(const float4*)&sinb[t * HDIM + d];
            float4 c1 = *(const float4*)&cosb[t * HDIM + 64 + d];
            float4 s1 = *(const float4*)&sinb[t * HDIM + 64 + d];
            float4 nlo, nhi;
            nlo.x = lo.x * c0.x - hi.x * s0.x;  nhi.x = hi.x * c1.x + lo.x * s1.x;
            nlo.y = lo.y * c0.y - hi.y * s0.y;  nhi.y = hi.y * c1.y + lo.y * s1.y;
            nlo.z = lo.z * c0.z - hi.z * s0.z;  nhi.z = hi.z * c1.z + lo.z * s1.z;
            nlo.w = lo.w * c0.w - hi.w * s0.w;  nhi.w = hi.w * c1.w + lo.w * s1.w;
            lo = nlo; hi = nhi;
        }
        *(float4*)&outp[d]      = lo;
        *(float4*)&outp[64 + d] = hi;
    }
}

// ---------------------------------------------------------------------------
// Output projection on mma.sync: out[m, n] row-major.
// ---------------------------------------------------------------------------
__global__ __launch_bounds__(256, 1)
void wo_mma_kernel(const __nv_bfloat16* __restrict__ ahi, const __nv_bfloat16* __restrict__ alo,
                   const __nv_bfloat16* __restrict__ whi, const __nv_bfloat16* __restrict__ wlo,
                   float* __restrict__ out)
{
    extern __shared__ char smem[];
    uint32_t sbase = smem_u32(smem);
    int tid = threadIdx.x;
    int n0 = blockIdx.x * 128, m0 = blockIdx.y * 128;

    const __nv_bfloat16* Ah = ahi + (size_t)m0 * KDIM;
    const __nv_bfloat16* Al = alo + (size_t)m0 * KDIM;
    const __nv_bfloat16* Bh = whi + (size_t)3 * HID * KDIM + (size_t)n0 * KDIM;
    const __nv_bfloat16* Bl = wlo + (size_t)3 * HID * KDIM + (size_t)n0 * KDIM;

    float acc[4][4][4];
#pragma unroll
    for (int i = 0; i < 4; i++)
#pragma unroll
        for (int j = 0; j < 4; j++)
#pragma unroll
            for (int c = 0; c < 4; c++) acc[i][j][c] = 0.f;

    mma_gemm_tile(Ah, Al, Bh, Bl, sbase, acc);

    float* Cs = (float*)smem;
    acc_to_smem(Cs, acc);
    __syncthreads();

    int r = tid >> 1, half = tid & 1;
    float* outp = out + (size_t)(m0 + r) * HID + n0 + half * 64;
#pragma unroll
    for (int j = 0; j < 64; j += 4)
        *(float4*)&outp[j] = *(float4*)&Cs[r * 132 + half * 64 + j];
}

// ---------------------------------------------------------------------------
// Flash attention (fp32), causal. Br=Bc=64, D=128. 256 threads (8 warps).
// (unchanged from the passing round)
// ---------------------------------------------------------------------------
#define FL_SMEM_FLOATS (64*128 + 64*132 + 64*132 + 64*64)

__global__ __launch_bounds__(256, 1)
void flash_kernel(const float* __restrict__ Qg, const float* __restrict__ Kg,
                  const float* __restrict__ Vg, float* __restrict__ Og)
{
    extern __shared__ float sm[];
    float* Qs = sm;                    // [64][128]
    float* Ks = Qs + 64 * 128;         // [64][132]
    float* Vs = Ks + 64 * 132;         // [64][132]
    float* Ps = Vs + 64 * 132;         // [64][64]

    int tid = threadIdx.x, lane = tid & 31, w = tid >> 5;
    int bh = blockIdx.y;
    int qi = gridDim.x - 1 - blockIdx.x;   // heavy tiles scheduled first
    int row0 = qi * 64;

    const float* Qb = Qg + (size_t)bh * T_SEQ * HDIM;
    const float* Kb = Kg + (size_t)bh * T_SEQ * HDIM;
    const float* Vb = Vg + (size_t)bh * T_SEQ * HDIM;

#pragma unroll
    for (int i = 0; i < 8; i++) {
        int e = tid + i * 256;
        int r = e >> 5, c4 = e & 31;
        *(float4*)&Qs[r * 128 + c4 * 4] = *(const float4*)&Qb[(row0 + r) * HDIM + c4 * 4];
    }

    float o[8][4];
    float mrow[8], lrow[8];
#pragma unroll
    for (int r = 0; r < 8; r++) {
        mrow[r] = -1e30f; lrow[r] = 0.f;
        o[r][0] = o[r][1] = o[r][2] = o[r][3] = 0.f;
    }
    const float scale = 0.08838834764831845f;   // 1/sqrt(128)

    for (int j = 0; j <= qi; j++) {
        __syncthreads();
#pragma unroll
        for (int i = 0; i < 8; i++) {
            int e = tid + i * 256;
            int r = e >> 5, c4 = e & 31;
            *(float4*)&Ks[r * 132 + c4 * 4] = *(const float4*)&Kb[(j * 64 + r) * HDIM + c4 * 4];
            *(float4*)&Vs[r * 132 + c4 * 4] = *(const float4*)&Vb[(j * 64 + r) * HDIM + c4 * 4];
        }
        __syncthreads();

        float s0[8], s1[8];
#pragma unroll
        for (int r = 0; r < 8; r++) { s0[r] = 0.f; s1[r] = 0.f; }
        for (int k4 = 0; k4 < 128; k4 += 4) {
            float4 kv0 = *(const float4*)&Ks[lane * 132 + k4];
            float4 kv1 = *(const float4*)&Ks[(lane + 32) * 132 + k4];
#pragma unroll
            for (int r = 0; r < 8; r++) {
                float4 qv = *(const float4*)&Qs[(w * 8 + r) * 128 + k4];
                s0[r] += qv.x * kv0.x + qv.y * kv0.y + qv.z * kv0.z + qv.w * kv0.w;
                s1[r] += qv.x * kv1.x + qv.y * kv1.y + qv.z * kv1.z + qv.w * kv1.w;
            }
        }

        bool diag = (j == qi);
#pragma unroll
        for (int r = 0; r < 8; r++) {
            float v0 = s0[r] * scale, v1 = s1[r] * scale;
            if (diag) {
                int gi = w * 8 + r;
                if (lane > gi)      v0 = -1e30f;
                if (lane + 32 > gi) v1 = -1e30f;
            }
            float mx = fmaxf(v0, v1);
#pragma unroll
            for (int off = 16; off > 0; off >>= 1)
                mx = fmaxf(mx, __shfl_xor_sync(0xffffffffu, mx, off));
            float mnew = fmaxf(mrow[r], mx);
            float corr = __expf(mrow[r] - mnew);
            float p0 = __expf(v0 - mnew);
            float p1 = __expf(v1 - mnew);
            float sum = p0 + p1;
#pragma unroll
            for (int off = 16; off > 0; off >>= 1)
                sum += __shfl_xor_sync(0xffffffffu, sum, off);
            lrow[r] = lrow[r] * corr + sum;
            mrow[r] = mnew;
            o[r][0] *= corr; o[r][1] *= corr; o[r][2] *= corr; o[r][3] *= corr;
            Ps[(w * 8 + r) * 64 + lane]      = p0;
            Ps[(w * 8 + r) * 64 + lane + 32] = p1;
        }
        __syncwarp();

        for (int c4 = 0; c4 < 64; c4 += 4) {
            float4 va = *(const float4*)&Vs[(c4 + 0) * 132 + lane * 4];
            float4 vb = *(const float4*)&Vs[(c4 + 1) * 132 + lane * 4];
            float4 vc = *(const float4*)&Vs[(c4 + 2) * 132 + lane * 4];
            float4 vd = *(const float4*)&Vs[(c4 + 3) * 132 + lane * 4];
#pragma unroll
            for (int r = 0; r < 8; r++) {
                float4 p = *(const float4*)&Ps[(w * 8 + r) * 64 + c4];
                o[r][0] += p.x * va.x + p.y * vb.x + p.z * vc.x + p.w * vd.x;
                o[r][1] += p.x * va.y + p.y * vb.y + p.z * vc.y + p.w * vd.y;
                o[r][2] += p.x * va.z + p.y * vb.z + p.z * vc.z + p.w * vd.z;
                o[r][3] += p.x * va.w + p.y * vb.w + p.z * vc.w + p.w * vd.w;
            }
        }
        __syncwarp();
    }

    int b = bh >> 4, h = bh & 15;
#pragma unroll
    for (int r = 0; r < 8; r++) {
        float inv = 1.f / lrow[r];
        int t = row0 + w * 8 + r;
        float4 val = make_float4(o[r][0] * inv, o[r][1] * inv, o[r][2] * inv, o[r][3] * inv);
        *(float4*)&Og[(size_t)(b * T_SEQ + t) * HID + h * HDIM + lane * 4] = val;
    }
}

// ---------------------------------------------------------------------------
extern "C" void kernel_launch(void* const* d_in, const int* in_sizes, int n_in,
                              void* d_out, int out_size)
{
    const float* x    = (const float*)d_in[0];
    const float* cosb = (const float*)d_in[1];
    const float* sinb = (const float*)d_in[2];
    const float* Wq   = (const float*)d_in[3];
    const float* Wk   = (const float*)d_in[4];
    const float* Wv   = (const float*)d_in[5];
    const float* Wo   = (const float*)d_in[6];
    float* out = (float*)d_out;

    float *q, *k, *v, *ao;
    __nv_bfloat16 *xhi, *xlo, *whi, *wlo;
    cudaGetSymbolAddress((void**)&q,   g_q);
    cudaGetSymbolAddress((void**)&k,   g_k);
    cudaGetSymbolAddress((void**)&v,   g_v);
    cudaGetSymbolAddress((void**)&ao,  g_ao);
    cudaGetSymbolAddress((void**)&xhi, g_xhi);
    cudaGetSymbolAddress((void**)&xlo, g_xlo);
    cudaGetSymbolAddress((void**)&whi, g_whi);
    cudaGetSymbolAddress((void**)&wlo, g_wlo);

    // 1) split activations + weights into bf16 hi/lo
    const int XN4 = MROWS * KDIM / 4;          // 2M
    const int WN4 = HID * KDIM / 4;            // 1M
    split_kernel<<<XN4 / 256, 256>>>(x, xhi, xlo, XN4);
    split_kernel<<<WN4 / 256, 256>>>(Wq, whi + 0 * (size_t)HID * KDIM, wlo + 0 * (size_t)HID * KDIM, WN4);
    split_kernel<<<WN4 / 256, 256>>>(Wk, whi + 1 * (size_t)HID * KDIM, wlo + 1 * (size_t)HID * KDIM, WN4);
    split_kernel<<<WN4 / 256, 256>>>(Wv, whi + 2 * (size_t)HID * KDIM, wlo + 2 * (size_t)HID * KDIM, WN4);
    split_kernel<<<WN4 / 256, 256>>>(Wo, whi + 3 * (size_t)HID * KDIM, wlo + 3 * (size_t)HID * KDIM, WN4);

    // 2) QKV projection + RoPE on mma.sync tensor cores
    cudaFuncSetAttribute(qkv_mma_kernel, cudaFuncAttributeMaxDynamicSharedMemorySize, GEMM_SMEM);
    qkv_mma_kernel<<<dim3(HID / 128, MROWS / 128, 3), 256, GEMM_SMEM>>>(
        xhi, xlo, whi, wlo, q, k, v, cosb, sinb);

    // 3) flash attention (fp32)
    const int FLASH_SMEM = FL_SMEM_FLOATS * (int)sizeof(float);   // 116736 B
    cudaFuncSetAttribute(flash_kernel, cudaFuncAttributeMaxDynamicSharedMemorySize, FLASH_SMEM);
    flash_kernel<<<dim3(T_SEQ / 64, BATCH * NHEAD), 256, FLASH_SMEM>>>(q, k, v, ao);

    // 4) split attention output, then output projection on mma.sync
    split_kernel<<<XN4 / 256, 256>>>(ao, xhi, xlo, XN4);
    cudaFuncSetAttribute(wo_mma_kernel, cudaFuncAttributeMaxDynamicSharedMemorySize, GEMM_SMEM);
    wo_mma_kernel<<<dim3(HID / 128, MROWS / 128), 256, GEMM_SMEM>>>(xhi, xlo, whi, wlo, out);
}

// round 10
// speedup vs baseline: 1.9715x; 1.3300x over previous
#include <cuda_runtime.h>
#include <cuda_bf16.h>
#include <cstdint>
#include <math.h>

// Problem constants
#define BATCH 2
#define T_SEQ 2048
#define HID   2048
#define NHEAD 16
#define HDIM  128
#define MROWS (BATCH * T_SEQ)   // 4096
#define KDIM  2048
#define NELEM (BATCH * NHEAD * T_SEQ * HDIM)   // 8M

// ---------------------------------------------------------------------------
// Scratch (device globals; allocation-free kernel_launch)
// ---------------------------------------------------------------------------
__device__ __nv_bfloat16 g_xhi[MROWS * KDIM];   // x split; later reused as ao split
__device__ __nv_bfloat16 g_xlo[MROWS * KDIM];
__device__ __nv_bfloat16 g_whi[4 * HID * KDIM]; // Wq,Wk,Wv,Wo hi
__device__ __nv_bfloat16 g_wlo[4 * HID * KDIM];
__device__ __nv_bfloat16 g_qhi[NELEM];          // [b,h][t][d], pre-scaled+RoPE
__device__ __nv_bfloat16 g_qlo[NELEM];
__device__ __nv_bfloat16 g_khi[NELEM];          // [b,h][t][d], RoPE
__device__ __nv_bfloat16 g_klo[NELEM];
__device__ __nv_bfloat16 g_vthi[NELEM];         // [b,h][d][t]  (transposed!)
__device__ __nv_bfloat16 g_vtlo[NELEM];

// ---------------------------------------------------------------------------
// PTX helpers (baseline PTX only)
// ---------------------------------------------------------------------------
__device__ __forceinline__ uint32_t smem_u32(const void* p) {
    uint32_t a;
    asm("{ .reg .u64 t; cvta.to.shared.u64 t, %1; cvt.u32.u64 %0, t; }" : "=r"(a) : "l"(p));
    return a;
}
#define LDM4(r, addr) \
    asm volatile("ldmatrix.sync.aligned.m8n8.x4.shared.b16 {%0,%1,%2,%3}, [%4];" \
        : "=r"((r)[0]), "=r"((r)[1]), "=r"((r)[2]), "=r"((r)[3]) : "r"(addr))
#define MMA_BF16(d, a, b0, b1) \
    asm volatile("mma.sync.aligned.m16n8k16.row.col.f32.bf16.bf16.f32 " \
        "{%0,%1,%2,%3}, {%4,%5,%6,%7}, {%8,%9}, {%0,%1,%2,%3};" \
        : "+f"((d)[0]), "+f"((d)[1]), "+f"((d)[2]), "+f"((d)[3]) \
        : "r"((a)[0]), "r"((a)[1]), "r"((a)[2]), "r"((a)[3]), "r"(b0), "r"(b1))
#define CP16(s, g) \
    asm volatile("cp.async.cg.shared.global [%0], [%1], 16;" \
        :: "r"(s), "l"(__cvta_generic_to_global(g)) : "memory")
#define CP_COMMIT() asm volatile("cp.async.commit_group;" ::: "memory")
#define CP_WAIT1()  asm volatile("cp.async.wait_group 1;" ::: "memory")
#define CP_WAIT0()  asm volatile("cp.async.wait_group 0;" ::: "memory")

__device__ __forceinline__ void split_store2(__nv_bfloat16* dh, __nv_bfloat16* dl,
                                             float a, float b) {
    __nv_bfloat16 ha = __float2bfloat16(a), hb = __float2bfloat16(b);
    __nv_bfloat16 la = __float2bfloat16(a - __bfloat162float(ha));
    __nv_bfloat16 lb = __float2bfloat16(b - __bfloat162float(hb));
    *(__nv_bfloat162*)dh = __nv_bfloat162(ha, hb);
    *(__nv_bfloat162*)dl = __nv_bfloat162(la, lb);
}

// ---------------------------------------------------------------------------
// fp32 -> (bf16 hi, bf16 lo) split, 4 elems/thread
// ---------------------------------------------------------------------------
struct alignas(8) bf16x4 { __nv_bfloat162 a, b; };

__global__ void split_kernel(const float* __restrict__ src,
                             __nv_bfloat16* __restrict__ hi,
                             __nv_bfloat16* __restrict__ lo, int n4)
{
    int i = blockIdx.x * blockDim.x + threadIdx.x;
    if (i >= n4) return;
    float4 v = ((const float4*)src)[i];
    __nv_bfloat16 h0 = __float2bfloat16(v.x), h1 = __float2bfloat16(v.y);
    __nv_bfloat16 h2 = __float2bfloat16(v.z), h3 = __float2bfloat16(v.w);
    __nv_bfloat16 l0 = __float2bfloat16(v.x - __bfloat162float(h0));
    __nv_bfloat16 l1 = __float2bfloat16(v.y - __bfloat162float(h1));
    __nv_bfloat16 l2 = __float2bfloat16(v.z - __bfloat162float(h2));
    __nv_bfloat16 l3 = __float2bfloat16(v.w - __bfloat162float(h3));
    bf16x4 hv, lv;
    hv.a = __nv_bfloat162(h0, h1); hv.b = __nv_bfloat162(h2, h3);
    lv.a = __nv_bfloat162(l0, l1); lv.b = __nv_bfloat162(l2, l3);
    ((bf16x4*)hi)[i] = hv;
    ((bf16x4*)lo)[i] = lv;
}

// ---------------------------------------------------------------------------
// mma.sync split-bf16 GEMM tile: C[128,128] = A[128,K] * B[128,K]^T (fp32 acc)
// 8 warps = 2(M) x 4(N); warp tile 64x32; BK=32; 3-stage cp.async ring,
// ONE __syncthreads per chunk (issue(c+2) after barrier: (c+2)%3==(c-1)%3,
// barrier orders it after compute(c-1)).
// ---------------------------------------------------------------------------
#define TILE_B    10240           // 128 * 40 * 2
#define STAGE_B   (4 * TILE_B)    // 40960
#define GEMM_SMEM (3 * STAGE_B)   // 122880

__device__ __forceinline__ void mma_gemm_tile(
    const __nv_bfloat16* __restrict__ Ah, const __nv_bfloat16* __restrict__ Al,
    const __nv_bfloat16* __restrict__ Bh, const __nv_bfloat16* __restrict__ Bl,
    uint32_t sbase, float acc[4][4][4])
{
    int tid = threadIdx.x, lane = tid & 31, w = tid >> 5;
    int wm = w & 1, wn = w >> 1;
    uint32_t r8 = lane & 7, mi = lane >> 3;
    uint32_t a_off = ((wm * 64 + ((mi & 1) << 3) + r8) * 40 + ((mi >> 1) << 3)) * 2;
    uint32_t b_off = ((wn * 32 + ((mi >> 1) << 3) + r8) * 40 + ((mi & 1) << 3)) * 2;

    int e0 = tid, e1 = tid + 256;
    int r0 = e0 >> 2, kq0 = e0 & 3;
    int r1 = e1 >> 2, kq1 = e1 & 3;
    uint32_t so0 = (uint32_t)((r0 * 40 + kq0 * 8) * 2);
    uint32_t so1 = (uint32_t)((r1 * 40 + kq1 * 8) * 2);

    auto issue = [&](int c, int buf) {
        uint32_t sb = sbase + buf * STAGE_B;
        size_t gg0 = (size_t)r0 * KDIM + c * 32 + kq0 * 8;
        size_t gg1 = (size_t)r1 * KDIM + c * 32 + kq1 * 8;
        CP16(sb + 0 * TILE_B + so0, Ah + gg0);
        CP16(sb + 0 * TILE_B + so1, Ah + gg1);
        CP16(sb + 1 * TILE_B + so0, Al + gg0);
        CP16(sb + 1 * TILE_B + so1, Al + gg1);
        CP16(sb + 2 * TILE_B + so0, Bh + gg0);
        CP16(sb + 2 * TILE_B + so1, Bh + gg1);
        CP16(sb + 3 * TILE_B + so0, Bl + gg0);
        CP16(sb + 3 * TILE_B + so1, Bl + gg1);
    };

    auto compute = [&](int buf) {
        uint32_t sb = sbase + buf * STAGE_B;
#pragma unroll
        for (int ks = 0; ks < 2; ks++) {
            uint32_t k0b = ks * 32;
            uint32_t bh[8], bl[8];
#pragma unroll
            for (int p = 0; p < 2; p++) {
                LDM4(&bh[p * 4], sb + 2 * TILE_B + b_off + p * 1280 + k0b);
                LDM4(&bl[p * 4], sb + 3 * TILE_B + b_off + p * 1280 + k0b);
            }
#pragma unroll
            for (int ma = 0; ma < 4; ma++) {
                uint32_t ah[4], al[4];
                LDM4(ah, sb + 0 * TILE_B + a_off + ma * 1280 + k0b);
                LDM4(al, sb + 1 * TILE_B + a_off + ma * 1280 + k0b);
#pragma unroll
                for (int na = 0; na < 4; na++) {
                    int bi = (na >> 1) * 4 + (na & 1) * 2;
                    MMA_BF16(acc[ma][na], ah, bh[bi], bh[bi + 1]);
                    MMA_BF16(acc[ma][na], ah, bl[bi], bl[bi + 1]);
                    MMA_BF16(acc[ma][na], al, bh[bi], bh[bi + 1]);
                }
            }
        }
    };

    const int NCH = KDIM / 32;   // 64
    issue(0, 0); CP_COMMIT();
    issue(1, 1); CP_COMMIT();
    for (int c = 0; c < NCH; c++) {
        if (c == NCH - 1) { CP_WAIT0(); } else { CP_WAIT1(); }
        __syncthreads();
        if (c + 2 < NCH) { issue(c + 2, (c + 2) % 3); CP_COMMIT(); }
        compute(c % 3);
    }
    __syncthreads();   // protect smem reuse by caller epilogue
}

// stage acc -> smem float[128][132]
__device__ __forceinline__ void acc_to_smem(float* Cs, float acc[4][4][4])
{
    int tid = threadIdx.x, lane = tid & 31, w = tid >> 5;
    int wm = w & 1, wn = w >> 1;
    int g = lane >> 2, tg = lane & 3;
#pragma unroll
    for (int ma = 0; ma < 4; ma++)
#pragma unroll
        for (int na = 0; na < 4; na++) {
            int col = wn * 32 + na * 8 + tg * 2;
            int row = wm * 64 + ma * 16 + g;
            *(float2*)&Cs[row * 132 + col]       = make_float2(acc[ma][na][0], acc[ma][na][1]);
            *(float2*)&Cs[(row + 8) * 132 + col] = make_float2(acc[ma][na][2], acc[ma][na][3]);
        }
}

// ---------------------------------------------------------------------------
// QKV projection: GEMM + RoPE(+scale) + split-bf16 stores in flash layouts.
// grid (16, 32, 3): n-block = head, m-block = 128 tokens, z = Q/K/V.
// ---------------------------------------------------------------------------
__global__ __launch_bounds__(256, 1)
void qkv_mma_kernel(const __nv_bfloat16* __restrict__ xhi, const __nv_bfloat16* __restrict__ xlo,
                    const __nv_bfloat16* __restrict__ whi, const __nv_bfloat16* __restrict__ wlo,
                    const float* __restrict__ cosb, const float* __restrict__ sinb)
{
    extern __shared__ char smem[];
    uint32_t sbase = smem_u32(smem);
    int tid = threadIdx.x;
    int z = blockIdx.z;
    int n0 = blockIdx.x * 128, m0 = blockIdx.y * 128;
    int h = n0 >> 7;
    int b = m0 >> 11, t0 = m0 & 2047;
    int bh = b * NHEAD + h;

    const __nv_bfloat16* Ah = xhi + (size_t)m0 * KDIM;
    const __nv_bfloat16* Al = xlo + (size_t)m0 * KDIM;
    const __nv_bfloat16* Bh = whi + (size_t)z * HID * KDIM + (size_t)n0 * KDIM;
    const __nv_bfloat16* Bl = wlo + (size_t)z * HID * KDIM + (size_t)n0 * KDIM;

    float acc[4][4][4];
#pragma unroll
    for (int i = 0; i < 4; i++)
#pragma unroll
        for (int j = 0; j < 4; j++)
#pragma unroll
            for (int c = 0; c < 4; c++) acc[i][j][c] = 0.f;

    mma_gemm_tile(Ah, Al, Bh, Bl, sbase, acc);

    float* Cs = (float*)smem;
    acc_to_smem(Cs, acc);
    __syncthreads();

    if (z < 2) {
        // RoPE (+scale for Q), split, store [bh][t][d]
        __nv_bfloat16* dh = (z == 0 ? g_qhi : g_khi) + ((size_t)bh * T_SEQ + t0) * HDIM;
        __nv_bfloat16* dl = (z == 0 ? g_qlo : g_klo) + ((size_t)bh * T_SEQ + t0) * HDIM;
        const float qscale = (z == 0) ? 0.08838834764831845f : 1.0f;
        int r = tid >> 1, half = tid & 1;
        int t = t0 + r;
        int d0 = half * 32;
        __nv_bfloat16* rowh = dh + (size_t)r * HDIM;
        __nv_bfloat16* rowl = dl + (size_t)r * HDIM;
#pragma unroll
        for (int j = 0; j < 32; j += 2) {
            int d = d0 + j;
            float a0 = Cs[r * 132 + d],      a1 = Cs[r * 132 + d + 1];
            float b0 = Cs[r * 132 + d + 64], b1 = Cs[r * 132 + d + 65];
            float c00 = cosb[t * HDIM + d],      s00 = sinb[t * HDIM + d];
            float c01 = cosb[t * HDIM + d + 1],  s01 = sinb[t * HDIM + d + 1];
            float c10 = cosb[t * HDIM + 64 + d],     s10 = sinb[t * HDIM + 64 + d];
            float c11 = cosb[t * HDIM + 64 + d + 1], s11 = sinb[t * HDIM + 64 + d + 1];
            float o00 = (a0 * c00 - b0 * s00) * qscale;
            float o01 = (a1 * c01 - b1 * s01) * qscale;
            float o10 = (b0 * c10 + a0 * s10) * qscale;
            float o11 = (b1 * c11 + a1 * s11) * qscale;
            split_store2(rowh + d, rowl + d, o00, o01);
            split_store2(rowh + 64 + d, rowl + 64 + d, o10, o11);
        }
    } else {
        // V transpose: store [bh][d][t]
        __nv_bfloat16* dh = g_vthi + (size_t)bh * HDIM * T_SEQ;
        __nv_bfloat16* dl = g_vtlo + (size_t)bh * HDIM * T_SEQ;
#pragma unroll 4
        for (int i = 0; i < 64; i++) {
            int d = (i & 31) * 4 + (tid >> 6);
            int tl = (i >> 5) * 64 + (tid & 63);
            float val = Cs[tl * 132 + d];
            __nv_bfloat16 hv = __float2bfloat16(val);
            __nv_bfloat16 lv = __float2bfloat16(val - __bfloat162float(hv));
            dh[(size_t)d * T_SEQ + t0 + tl] = hv;
            dl[(size_t)d * T_SEQ + t0 + tl] = lv;
        }
    }
}

// ---------------------------------------------------------------------------
// Flash attention on mma.sync, split-bf16, causal. Br=128, Bc=64, D=128.
// 256 threads, 8 warps; warp w owns rows w*16..w*16+15 for the FULL 64 kv cols
// (softmax reductions stay inside 4-lane shfl groups). Single-buffered K/V.
// Output: split-bf16 into aohi/aolo [m][h*128+d] (= Wo GEMM A layout).
// ---------------------------------------------------------------------------
#define FS_QH 0
#define FS_QL 40960
#define FS_KH 81920
#define FS_KL 102400
#define FS_VH 122880
#define FS_VL 143360
#define FS_PH 163840
#define FS_PL 184320
#define FLASH_SMEM 204800

__global__ __launch_bounds__(256, 1)
void flash_hmma_kernel(const __nv_bfloat16* __restrict__ qhi, const __nv_bfloat16* __restrict__ qlo,
                       const __nv_bfloat16* __restrict__ khi, const __nv_bfloat16* __restrict__ klo,
                       const __nv_bfloat16* __restrict__ vthi, const __nv_bfloat16* __restrict__ vtlo,
                       __nv_bfloat16* __restrict__ aohi, __nv_bfloat16* __restrict__ aolo)
{
    extern __shared__ char smem[];
    uint32_t sbase = smem_u32(smem);
    int tid = threadIdx.x, lane = tid & 31, w = tid >> 5;
    int bh = blockIdx.y;
    int qi = gridDim.x - 1 - blockIdx.x;   // heavy tiles first
    int qrow0 = qi * 128;

    const __nv_bfloat16* qh_b = qhi + (size_t)bh * T_SEQ * HDIM;
    const __nv_bfloat16* ql_b = qlo + (size_t)bh * T_SEQ * HDIM;
    const __nv_bfloat16* kh_b = khi + (size_t)bh * T_SEQ * HDIM;
    const __nv_bfloat16* kl_b = klo + (size_t)bh * T_SEQ * HDIM;
    const __nv_bfloat16* vh_b = vthi + (size_t)bh * HDIM * T_SEQ;
    const __nv_bfloat16* vl_b = vtlo + (size_t)bh * HDIM * T_SEQ;

    // Stage Q (128 x 128, hi+lo) into 4 chunks [128][40]
#pragma unroll
    for (int i = 0; i < 8; i++) {
        int e = tid + i * 256;
        int row = e >> 4, u = e & 15;
        const __nv_bfloat16* gq = qh_b + (size_t)(qrow0 + row) * HDIM + u * 8;
        uint32_t sa = sbase + FS_QH + (u >> 2) * 10240 + (row * 40 + (u & 3) * 8) * 2;
        CP16(sa, gq);
        CP16(sa + (FS_QL - FS_QH), ql_b + (size_t)(qrow0 + row) * HDIM + u * 8);
    }
    CP_COMMIT();

    uint32_t r8 = lane & 7, mi = lane >> 3;
    int tg = lane & 3, g = lane >> 2;
    uint32_t aoff = ((w * 16 + (mi & 1) * 8 + r8) * 40 + (mi >> 1) * 8) * 2;
    uint32_t boff = (((mi >> 1) * 8 + r8) * 40 + (mi & 1) * 8) * 2;

    float oacc[16][4];
#pragma unroll
    for (int i = 0; i < 16; i++)
#pragma unroll
        for (int c = 0; c < 4; c++) oacc[i][c] = 0.f;
    float mrow0 = -1e30f, mrow1 = -1e30f, lrow0 = 0.f, lrow1 = 0.f;

    int row0l = w * 16 + g;                // local row (0..127)
    int gr0 = qrow0 + row0l, gr1 = gr0 + 8;
    int jmax = 2 * qi + 1;

    for (int j = 0; j <= jmax; j++) {
        // load K tile (64x128 hi/lo) and V^T tile (128x64 hi/lo)
#pragma unroll
        for (int i = 0; i < 4; i++) {
            int e = tid + i * 256;
            int row = e >> 4, u = e & 15;
            uint32_t sa = sbase + FS_KH + (u >> 2) * 5120 + (row * 40 + (u & 3) * 8) * 2;
            size_t go = (size_t)(j * 64 + row) * HDIM + u * 8;
            CP16(sa, kh_b + go);
            CP16(sa + (FS_KL - FS_KH), kl_b + go);
        }
#pragma unroll
        for (int i = 0; i < 4; i++) {
            int e = tid + i * 256;
            int d = e >> 3, u = e & 7;
            uint32_t sa = sbase + FS_VH + (u >> 2) * 10240 + (d * 40 + (u & 3) * 8) * 2;
            size_t go = (size_t)d * T_SEQ + j * 64 + u * 8;
            CP16(sa, vh_b + go);
            CP16(sa + (FS_VL - FS_VH), vl_b + go);
        }
        CP_COMMIT(); CP_WAIT0();
        __syncthreads();

        // S = Q K^T (64 cols per warp, 16 rows)
        float sacc[8][4];
#pragma unroll
        for (int i = 0; i < 8; i++)
#pragma unroll
            for (int c = 0; c < 4; c++) sacc[i][c] = 0.f;

#pragma unroll
        for (int ks = 0; ks < 8; ks++) {
            uint32_t ko = (ks & 1) * 32;
            uint32_t qh4[4], ql4[4];
            LDM4(qh4, sbase + FS_QH + (ks >> 1) * 10240 + aoff + ko);
            LDM4(ql4, sbase + FS_QL + (ks >> 1) * 10240 + aoff + ko);
#pragma unroll
            for (int nb = 0; nb < 4; nb++) {
                uint32_t kh4[4], kl4[4];
                LDM4(kh4, sbase + FS_KH + (ks >> 1) * 5120 + boff + nb * 1280 + ko);
                LDM4(kl4, sbase + FS_KL + (ks >> 1) * 5120 + boff + nb * 1280 + ko);
                MMA_BF16(sacc[nb * 2],     qh4, kh4[0], kh4[1]);
                MMA_BF16(sacc[nb * 2],     ql4, kh4[0], kh4[1]);
                MMA_BF16(sacc[nb * 2],     qh4, kl4[0], kl4[1]);
                MMA_BF16(sacc[nb * 2 + 1], qh4, kh4[2], kh4[3]);
                MMA_BF16(sacc[nb * 2 + 1], ql4, kh4[2], kh4[3]);
                MMA_BF16(sacc[nb * 2 + 1], qh4, kl4[2], kl4[3]);
            }
        }

        // causal mask (only the two diagonal tiles need it)
        if (j >= 2 * qi) {
#pragma unroll
            for (int na = 0; na < 8; na++) {
                int gc = j * 64 + na * 8 + tg * 2;
                if (gc     > gr0) sacc[na][0] = -1e30f;
                if (gc + 1 > gr0) sacc[na][1] = -1e30f;
                if (gc     > gr1) sacc[na][2] = -1e30f;
                if (gc + 1 > gr1) sacc[na][3] = -1e30f;
            }
        }

        // online softmax (rows gr0, gr1); reduce over 4-lane tg group
        float m0 = -1e30f, m1 = -1e30f;
#pragma unroll
        for (int na = 0; na < 8; na++) {
            m0 = fmaxf(m0, fmaxf(sacc[na][0], sacc[na][1]));
            m1 = fmaxf(m1, fmaxf(sacc[na][2], sacc[na][3]));
        }
        m0 = fmaxf(m0, __shfl_xor_sync(0xffffffffu, m0, 1));
        m0 = fmaxf(m0, __shfl_xor_sync(0xffffffffu, m0, 2));
        m1 = fmaxf(m1, __shfl_xor_sync(0xffffffffu, m1, 1));
        m1 = fmaxf(m1, __shfl_xor_sync(0xffffffffu, m1, 2));
        float mn0 = fmaxf(mrow0, m0), mn1 = fmaxf(mrow1, m1);
        float cr0 = __expf(mrow0 - mn0), cr1 = __expf(mrow1 - mn1);
        float s0 = 0.f, s1 = 0.f;
#pragma unroll
        for (int na = 0; na < 8; na++) {
            float p00 = __expf(sacc[na][0] - mn0);
            float p01 = __expf(sacc[na][1] - mn0);
            float p10 = __expf(sacc[na][2] - mn1);
            float p11 = __expf(sacc[na][3] - mn1);
            s0 += p00 + p01; s1 += p10 + p11;
            // split-store P to smem (chunked [128][40], warp-private rows)
            char* baseh = smem + FS_PH + (na >> 2) * 10240;
            char* basel = smem + FS_PL + (na >> 2) * 10240;
            uint32_t cw = (na & 3) * 8 + tg * 2;
            split_store2((__nv_bfloat16*)(baseh + (row0l * 40 + cw) * 2),
                         (__nv_bfloat16*)(basel + (row0l * 40 + cw) * 2), p00, p01);
            split_store2((__nv_bfloat16*)(baseh + ((row0l + 8) * 40 + cw) * 2),
                         (__nv_bfloat16*)(basel + ((row0l + 8) * 40 + cw) * 2), p10, p11);
        }
        s0 += __shfl_xor_sync(0xffffffffu, s0, 1);
        s0 += __shfl_xor_sync(0xffffffffu, s0, 2);
        s1 += __shfl_xor_sync(0xffffffffu, s1, 1);
        s1 += __shfl_xor_sync(0xffffffffu, s1, 2);
        lrow0 = lrow0 * cr0 + s0;  lrow1 = lrow1 * cr1 + s1;
        mrow0 = mn0;               mrow1 = mn1;
#pragma unroll
        for (int na = 0; na < 16; na++) {
            oacc[na][0] *= cr0; oacc[na][1] *= cr0;
            oacc[na][2] *= cr1; oacc[na][3] *= cr1;
        }
        __syncwarp();

        // O += P V  (A = P rows of this warp; B = V^T, n = d 128)
#pragma unroll
        for (int kvs = 0; kvs < 4; kvs++) {
            uint32_t ko = (kvs & 1) * 32;
            uint32_t ph4[4], pl4[4];
            LDM4(ph4, sbase + FS_PH + (kvs >> 1) * 10240 + aoff + ko);
            LDM4(pl4, sbase + FS_PL + (kvs >> 1) * 10240 + aoff + ko);
#pragma unroll
            for (int nb = 0; nb < 8; nb++) {
                uint32_t vh4[4], vl4[4];
                LDM4(vh4, sbase + FS_VH + (kvs >> 1) * 10240 + boff + nb * 1280 + ko);
                LDM4(vl4, sbase + FS_VL + (kvs >> 1) * 10240 + boff + nb * 1280 + ko);
                MMA_BF16(oacc[nb * 2],     ph4, vh4[0], vh4[1]);
                MMA_BF16(oacc[nb * 2],     pl4, vh4[0], vh4[1]);
                MMA_BF16(oacc[nb * 2],     ph4, vl4[0], vl4[1]);
                MMA_BF16(oacc[nb * 2 + 1], ph4, vh4[2], vh4[3]);
                MMA_BF16(oacc[nb * 2 + 1], pl4, vh4[2], vh4[3]);
                MMA_BF16(oacc[nb * 2 + 1], ph4, vl4[2], vl4[3]);
            }
        }
        __syncthreads();   // all warps done with K/V before next-tile loads
    }

    // epilogue: normalize, split, store into Wo's A layout [m][h*128+d]
    int bb = bh >> 4, hh = bh & 15;
    float inv0 = 1.f / lrow0, inv1 = 1.f / lrow1;
    size_t m0i = (size_t)(bb * T_SEQ + gr0) * HID + hh * HDIM;
    size_t m1i = (size_t)(bb * T_SEQ + gr1) * HID + hh * HDIM;
#pragma unroll
    for (int na = 0; na < 16; na++) {
        int col = na * 8 + tg * 2;
        split_store2(aohi + m0i + col, aolo + m0i + col,
                     oacc[na][0] * inv0, oacc[na][1] * inv0);
        split_store2(aohi + m1i + col, aolo + m1i + col,
                     oacc[na][2] * inv1, oacc[na][3] * inv1);
    }
}

// ---------------------------------------------------------------------------
// Output projection on mma.sync: out[m, n] row-major fp32.
// ---------------------------------------------------------------------------
__global__ __launch_bounds__(256, 1)
void wo_mma_kernel(const __nv_bfloat16* __restrict__ ahi, const __nv_bfloat16* __restrict__ alo,
                   const __nv_bfloat16* __restrict__ whi, const __nv_bfloat16* __restrict__ wlo,
                   float* __restrict__ out)
{
    extern __shared__ char smem[];
    uint32_t sbase = smem_u32(smem);
    int tid = threadIdx.x;
    int n0 = blockIdx.x * 128, m0 = blockIdx.y * 128;

    const __nv_bfloat16* Ah = ahi + (size_t)m0 * KDIM;
    const __nv_bfloat16* Al = alo + (size_t)m0 * KDIM;
    const __nv_bfloat16* Bh = whi + (size_t)3 * HID * KDIM + (size_t)n0 * KDIM;
    const __nv_bfloat16* Bl = wlo + (size_t)3 * HID * KDIM + (size_t)n0 * KDIM;

    float acc[4][4][4];
#pragma unroll
    for (int i = 0; i < 4; i++)
#pragma unroll
        for (int j = 0; j < 4; j++)
#pragma unroll
            for (int c = 0; c < 4; c++) acc[i][j][c] = 0.f;

    mma_gemm_tile(Ah, Al, Bh, Bl, sbase, acc);

    float* Cs = (float*)smem;
    acc_to_smem(Cs, acc);
    __syncthreads();

    int r = tid >> 1, half = tid & 1;
    float* outp = out + (size_t)(m0 + r) * HID + n0 + half * 64;
#pragma unroll
    for (int j = 0; j < 64; j += 4)
        *(float4*)&outp[j] = *(float4*)&Cs[r * 132 + half * 64 + j];
}

// ---------------------------------------------------------------------------
extern "C" void kernel_launch(void* const* d_in, const int* in_sizes, int n_in,
                              void* d_out, int out_size)
{
    const float* x    = (const float*)d_in[0];
    const float* cosb = (const float*)d_in[1];
    const float* sinb = (const float*)d_in[2];
    const float* Wq   = (const float*)d_in[3];
    const float* Wk   = (const float*)d_in[4];
    const float* Wv   = (const float*)d_in[5];
    const float* Wo   = (const float*)d_in[6];
    float* out = (float*)d_out;

    __nv_bfloat16 *xhi, *xlo, *whi, *wlo;
    __nv_bfloat16 *qhi, *qlo, *khi, *klo, *vthi, *vtlo;
    cudaGetSymbolAddress((void**)&xhi, g_xhi);
    cudaGetSymbolAddress((void**)&xlo, g_xlo);
    cudaGetSymbolAddress((void**)&whi, g_whi);
    cudaGetSymbolAddress((void**)&wlo, g_wlo);
    cudaGetSymbolAddress((void**)&qhi, g_qhi);
    cudaGetSymbolAddress((void**)&qlo, g_qlo);
    cudaGetSymbolAddress((void**)&khi, g_khi);
    cudaGetSymbolAddress((void**)&klo, g_klo);
    cudaGetSymbolAddress((void**)&vthi, g_vthi);
    cudaGetSymbolAddress((void**)&vtlo, g_vtlo);

    // 1) split x and weights to bf16 hi/lo
    const int XN4 = MROWS * KDIM / 4;
    const int WN4 = HID * KDIM / 4;
    split_kernel<<<XN4 / 256, 256>>>(x, xhi, xlo, XN4);
    split_kernel<<<WN4 / 256, 256>>>(Wq, whi + 0 * (size_t)HID * KDIM, wlo + 0 * (size_t)HID * KDIM, WN4);
    split_kernel<<<WN4 / 256, 256>>>(Wk, whi + 1 * (size_t)HID * KDIM, wlo + 1 * (size_t)HID * KDIM, WN4);
    split_kernel<<<WN4 / 256, 256>>>(Wv, whi + 2 * (size_t)HID * KDIM, wlo + 2 * (size_t)HID * KDIM, WN4);
    split_kernel<<<WN4 / 256, 256>>>(Wo, whi + 3 * (size_t)HID * KDIM, wlo + 3 * (size_t)HID * KDIM, WN4);

    // 2) QKV projection + RoPE + layout/split fusion
    cudaFuncSetAttribute(qkv_mma_kernel, cudaFuncAttributeMaxDynamicSharedMemorySize, GEMM_SMEM);
    qkv_mma_kernel<<<dim3(HID / 128, MROWS / 128, 3), 256, GEMM_SMEM>>>(
        xhi, xlo, whi, wlo, cosb, sinb);

    // 3) flash attention (HMMA split-bf16); output -> g_xhi/g_xlo (reused)
    cudaFuncSetAttribute(flash_hmma_kernel, cudaFuncAttributeMaxDynamicSharedMemorySize, FLASH_SMEM);
    flash_hmma_kernel<<<dim3(T_SEQ / 128, BATCH * NHEAD), 256, FLASH_SMEM>>>(
        qhi, qlo, khi, klo, vthi, vtlo, xhi, xlo);

    // 4) output projection
    cudaFuncSetAttribute(wo_mma_kernel, cudaFuncAttributeMaxDynamicSharedMemorySize, GEMM_SMEM);
    wo_mma_kernel<<<dim3(HID / 128, MROWS / 128), 256, GEMM_SMEM>>>(xhi, xlo, whi, wlo, out);
}

// round 11
// speedup vs baseline: 2.4408x; 1.2381x over previous
#include <cuda_runtime.h>
#include <cuda_bf16.h>
#include <cuda_fp16.h>
#include <cstdint>
#include <math.h>

// Problem constants
#define BATCH 2
#define T_SEQ 2048
#define HID   2048
#define NHEAD 16
#define HDIM  128
#define MROWS (BATCH * T_SEQ)   // 4096
#define KDIM  2048
#define NELEM (BATCH * NHEAD * T_SEQ * HDIM)   // 8M

// ---------------------------------------------------------------------------
// Scratch (device globals; allocation-free kernel_launch)
// ---------------------------------------------------------------------------
__device__ __half g_xh[MROWS * KDIM];           // x fp16; later reused as ao fp16
__device__ __half g_wh[4 * HID * KDIM];         // Wq,Wk,Wv,Wo hi (fp16)
__device__ __half g_wl[4 * HID * KDIM];         // residual lo (fp16)
__device__ __nv_bfloat16 g_qhi[NELEM];          // [b,h][t][d], pre-scaled+RoPE
__device__ __nv_bfloat16 g_qlo[NELEM];
__device__ __nv_bfloat16 g_khi[NELEM];          // [b,h][t][d], RoPE
__device__ __nv_bfloat16 g_klo[NELEM];
__device__ __nv_bfloat16 g_vthi[NELEM];         // [b,h][d][t]  (transposed!)
__device__ __nv_bfloat16 g_vtlo[NELEM];

// ---------------------------------------------------------------------------
// PTX helpers (baseline PTX only)
// ---------------------------------------------------------------------------
__device__ __forceinline__ uint32_t smem_u32(const void* p) {
    uint32_t a;
    asm("{ .reg .u64 t; cvta.to.shared.u64 t, %1; cvt.u32.u64 %0, t; }" : "=r"(a) : "l"(p));
    return a;
}
#define LDM4(r, addr) \
    asm volatile("ldmatrix.sync.aligned.m8n8.x4.shared.b16 {%0,%1,%2,%3}, [%4];" \
        : "=r"((r)[0]), "=r"((r)[1]), "=r"((r)[2]), "=r"((r)[3]) : "r"(addr))
#define MMA_BF16(d, a, b0, b1) \
    asm volatile("mma.sync.aligned.m16n8k16.row.col.f32.bf16.bf16.f32 " \
        "{%0,%1,%2,%3}, {%4,%5,%6,%7}, {%8,%9}, {%0,%1,%2,%3};" \
        : "+f"((d)[0]), "+f"((d)[1]), "+f"((d)[2]), "+f"((d)[3]) \
        : "r"((a)[0]), "r"((a)[1]), "r"((a)[2]), "r"((a)[3]), "r"(b0), "r"(b1))
#define MMA_F16(d, a, b0, b1) \
    asm volatile("mma.sync.aligned.m16n8k16.row.col.f32.f16.f16.f32 " \
        "{%0,%1,%2,%3}, {%4,%5,%6,%7}, {%8,%9}, {%0,%1,%2,%3};" \
        : "+f"((d)[0]), "+f"((d)[1]), "+f"((d)[2]), "+f"((d)[3]) \
        : "r"((a)[0]), "r"((a)[1]), "r"((a)[2]), "r"((a)[3]), "r"(b0), "r"(b1))
#define CP16(s, g) \
    asm volatile("cp.async.cg.shared.global [%0], [%1], 16;" \
        :: "r"(s), "l"(__cvta_generic_to_global(g)) : "memory")
#define CP_COMMIT() asm volatile("cp.async.commit_group;" ::: "memory")
#define CP_WAIT1()  asm volatile("cp.async.wait_group 1;" ::: "memory")
#define CP_WAIT0()  asm volatile("cp.async.wait_group 0;" ::: "memory")

__device__ __forceinline__ void split_store2(__nv_bfloat16* dh, __nv_bfloat16* dl,
                                             float a, float b) {
    __nv_bfloat16 ha = __float2bfloat16(a), hb = __float2bfloat16(b);
    __nv_bfloat16 la = __float2bfloat16(a - __bfloat162float(ha));
    __nv_bfloat16 lb = __float2bfloat16(b - __bfloat162float(hb));
    *(__nv_bfloat162*)dh = __nv_bfloat162(ha, hb);
    *(__nv_bfloat162*)dl = __nv_bfloat162(la, lb);
}

// ---------------------------------------------------------------------------
// fp32 -> fp16 hi (+ optional lo residual) conversion kernels
// ---------------------------------------------------------------------------
struct alignas(8) h2x2 { __half2 a, b; };

__global__ void cvt_h_kernel(const float* __restrict__ src,
                             __half* __restrict__ hi, int n4)
{
    int i = blockIdx.x * blockDim.x + threadIdx.x;
    if (i >= n4) return;
    float4 v = ((const float4*)src)[i];
    h2x2 hv;
    hv.a = __floats2half2_rn(v.x, v.y);
    hv.b = __floats2half2_rn(v.z, v.w);
    ((h2x2*)hi)[i] = hv;
}

__global__ void split_h_kernel(const float* __restrict__ src,
                               __half* __restrict__ hi,
                               __half* __restrict__ lo, int n4)
{
    int i = blockIdx.x * blockDim.x + threadIdx.x;
    if (i >= n4) return;
    float4 v = ((const float4*)src)[i];
    __half h0 = __float2half(v.x), h1 = __float2half(v.y);
    __half h2 = __float2half(v.z), h3 = __float2half(v.w);
    h2x2 hv, lv;
    hv.a = __half2(h0, h1); hv.b = __half2(h2, h3);
    lv.a = __floats2half2_rn(v.x - __half2float(h0), v.y - __half2float(h1));
    lv.b = __floats2half2_rn(v.z - __half2float(h2), v.w - __half2float(h3));
    ((h2x2*)hi)[i] = hv;
    ((h2x2*)lo)[i] = lv;
}

// ---------------------------------------------------------------------------
// mma.sync fp16 2-product GEMM tile: C[128,128] = A[128,K] * B[128,K]^T
// (fp32 acc). C = A*(Bhi+Blo); A single fp16, B split fp16 hi+lo.
// 8 warps = 2(M) x 4(N); warp tile 64x32; BK=32; 3-stage cp.async ring,
// one __syncthreads per chunk. smem: 3 stages x 3 tiles x 10240 B.
// ---------------------------------------------------------------------------
#define TILE_B    10240           // 128 * 40 * 2
#define STAGE_B   (3 * TILE_B)    // 30720
#define GEMM_SMEM (3 * STAGE_B)   // 92160

__device__ __forceinline__ void mma_gemm_tile(
    const __half* __restrict__ Ah,
    const __half* __restrict__ Bh, const __half* __restrict__ Bl,
    uint32_t sbase, float acc[4][4][4])
{
    int tid = threadIdx.x, lane = tid & 31, w = tid >> 5;
    int wm = w & 1, wn = w >> 1;
    uint32_t r8 = lane & 7, mi = lane >> 3;
    uint32_t a_off = ((wm * 64 + ((mi & 1) << 3) + r8) * 40 + ((mi >> 1) << 3)) * 2;
    uint32_t b_off = ((wn * 32 + ((mi >> 1) << 3) + r8) * 40 + ((mi & 1) << 3)) * 2;

    int e0 = tid, e1 = tid + 256;
    int r0 = e0 >> 2, kq0 = e0 & 3;
    int r1 = e1 >> 2, kq1 = e1 & 3;
    uint32_t so0 = (uint32_t)((r0 * 40 + kq0 * 8) * 2);
    uint32_t so1 = (uint32_t)((r1 * 40 + kq1 * 8) * 2);

    auto issue = [&](int c, int buf) {
        uint32_t sb = sbase + buf * STAGE_B;
        size_t gg0 = (size_t)r0 * KDIM + c * 32 + kq0 * 8;
        size_t gg1 = (size_t)r1 * KDIM + c * 32 + kq1 * 8;
        CP16(sb + 0 * TILE_B + so0, Ah + gg0);
        CP16(sb + 0 * TILE_B + so1, Ah + gg1);
        CP16(sb + 1 * TILE_B + so0, Bh + gg0);
        CP16(sb + 1 * TILE_B + so1, Bh + gg1);
        CP16(sb + 2 * TILE_B + so0, Bl + gg0);
        CP16(sb + 2 * TILE_B + so1, Bl + gg1);
    };

    auto compute = [&](int buf) {
        uint32_t sb = sbase + buf * STAGE_B;
#pragma unroll
        for (int ks = 0; ks < 2; ks++) {
            uint32_t k0b = ks * 32;
            uint32_t bh[8], bl[8];
#pragma unroll
            for (int p = 0; p < 2; p++) {
                LDM4(&bh[p * 4], sb + 1 * TILE_B + b_off + p * 1280 + k0b);
                LDM4(&bl[p * 4], sb + 2 * TILE_B + b_off + p * 1280 + k0b);
            }
#pragma unroll
            for (int ma = 0; ma < 4; ma++) {
                uint32_t ah[4];
                LDM4(ah, sb + 0 * TILE_B + a_off + ma * 1280 + k0b);
#pragma unroll
                for (int na = 0; na < 4; na++) {
                    int bi = (na >> 1) * 4 + (na & 1) * 2;
                    MMA_F16(acc[ma][na], ah, bh[bi], bh[bi + 1]);
                    MMA_F16(acc[ma][na], ah, bl[bi], bl[bi + 1]);
                }
            }
        }
    };

    const int NCH = KDIM / 32;   // 64
    issue(0, 0); CP_COMMIT();
    issue(1, 1); CP_COMMIT();
    for (int c = 0; c < NCH; c++) {
        if (c == NCH - 1) { CP_WAIT0(); } else { CP_WAIT1(); }
        __syncthreads();
        if (c + 2 < NCH) { issue(c + 2, (c + 2) % 3); CP_COMMIT(); }
        compute(c % 3);
    }
    __syncthreads();   // protect smem reuse by caller epilogue
}

// stage acc -> smem float[128][132]
__device__ __forceinline__ void acc_to_smem(float* Cs, float acc[4][4][4])
{
    int tid = threadIdx.x, lane = tid & 31, w = tid >> 5;
    int wm = w & 1, wn = w >> 1;
    int g = lane >> 2, tg = lane & 3;
#pragma unroll
    for (int ma = 0; ma < 4; ma++)
#pragma unroll
        for (int na = 0; na < 4; na++) {
            int col = wn * 32 + na * 8 + tg * 2;
            int row = wm * 64 + ma * 16 + g;
            *(float2*)&Cs[row * 132 + col]       = make_float2(acc[ma][na][0], acc[ma][na][1]);
            *(float2*)&Cs[(row + 8) * 132 + col] = make_float2(acc[ma][na][2], acc[ma][na][3]);
        }
}

// ---------------------------------------------------------------------------
// QKV projection: GEMM + RoPE(+scale) + split-bf16 stores in flash layouts.
// grid (16, 32, 3): n-block = head, m-block = 128 tokens, z = Q/K/V.
// ---------------------------------------------------------------------------
__global__ __launch_bounds__(256, 1)
void qkv_mma_kernel(const __half* __restrict__ xh,
                    const __half* __restrict__ wh, const __half* __restrict__ wl,
                    const float* __restrict__ cosb, const float* __restrict__ sinb)
{
    extern __shared__ char smem[];
    uint32_t sbase = smem_u32(smem);
    int tid = threadIdx.x;
    int z = blockIdx.z;
    int n0 = blockIdx.x * 128, m0 = blockIdx.y * 128;
    int h = n0 >> 7;
    int b = m0 >> 11, t0 = m0 & 2047;
    int bh = b * NHEAD + h;

    const __half* Ah = xh + (size_t)m0 * KDIM;
    const __half* Bh = wh + (size_t)z * HID * KDIM + (size_t)n0 * KDIM;
    const __half* Bl = wl + (size_t)z * HID * KDIM + (size_t)n0 * KDIM;

    float acc[4][4][4];
#pragma unroll
    for (int i = 0; i < 4; i++)
#pragma unroll
        for (int j = 0; j < 4; j++)
#pragma unroll
            for (int c = 0; c < 4; c++) acc[i][j][c] = 0.f;

    mma_gemm_tile(Ah, Bh, Bl, sbase, acc);

    float* Cs = (float*)smem;
    acc_to_smem(Cs, acc);
    __syncthreads();

    if (z < 2) {
        // RoPE (+scale for Q), split, store [bh][t][d]
        __nv_bfloat16* dh = (z == 0 ? g_qhi : g_khi) + ((size_t)bh * T_SEQ + t0) * HDIM;
        __nv_bfloat16* dl = (z == 0 ? g_qlo : g_klo) + ((size_t)bh * T_SEQ + t0) * HDIM;
        const float qscale = (z == 0) ? 0.08838834764831845f : 1.0f;
        int r = tid >> 1, half = tid & 1;
        int t = t0 + r;
        int d0 = half * 32;
        __nv_bfloat16* rowh = dh + (size_t)r * HDIM;
        __nv_bfloat16* rowl = dl + (size_t)r * HDIM;
#pragma unroll
        for (int j = 0; j < 32; j += 2) {
            int d = d0 + j;
            float a0 = Cs[r * 132 + d],      a1 = Cs[r * 132 + d + 1];
            float b0 = Cs[r * 132 + d + 64], b1 = Cs[r * 132 + d + 65];
            float c00 = cosb[t * HDIM + d],      s00 = sinb[t * HDIM + d];
            float c01 = cosb[t * HDIM + d + 1],  s01 = sinb[t * HDIM + d + 1];
            float c10 = cosb[t * HDIM + 64 + d],     s10 = sinb[t * HDIM + 64 + d];
            float c11 = cosb[t * HDIM + 64 + d + 1], s11 = sinb[t * HDIM + 64 + d + 1];
            float o00 = (a0 * c00 - b0 * s00) * qscale;
            float o01 = (a1 * c01 - b1 * s01) * qscale;
            float o10 = (b0 * c10 + a0 * s10) * qscale;
            float o11 = (b1 * c11 + a1 * s11) * qscale;
            split_store2(rowh + d, rowl + d, o00, o01);
            split_store2(rowh + 64 + d, rowl + 64 + d, o10, o11);
        }
    } else {
        // V transpose: store [bh][d][t]
        __nv_bfloat16* dh = g_vthi + (size_t)bh * HDIM * T_SEQ;
        __nv_bfloat16* dl = g_vtlo + (size_t)bh * HDIM * T_SEQ;
#pragma unroll 4
        for (int i = 0; i < 64; i++) {
            int d = (i & 31) * 4 + (tid >> 6);
            int tl = (i >> 5) * 64 + (tid & 63);
            float val = Cs[tl * 132 + d];
            __nv_bfloat16 hv = __float2bfloat16(val);
            __nv_bfloat16 lv = __float2bfloat16(val - __bfloat162float(hv));
            dh[(size_t)d * T_SEQ + t0 + tl] = hv;
            dl[(size_t)d * T_SEQ + t0 + tl] = lv;
        }
    }
}

// ---------------------------------------------------------------------------
// Flash attention on mma.sync, split-bf16, causal. Br=128, Bc=64, D=128.
// 256 threads, 8 warps; warp w owns rows w*16..w*16+15 for the FULL 64 kv cols
// (softmax reductions stay inside 4-lane shfl groups). Single-buffered K/V.
// Output: fp16 into aoh [m][h*128+d] (= Wo GEMM A layout).
// ---------------------------------------------------------------------------
#define FS_QH 0
#define FS_QL 40960
#define FS_KH 81920
#define FS_KL 102400
#define FS_VH 122880
#define FS_VL 143360
#define FS_PH 163840
#define FS_PL 184320
#define FLASH_SMEM 204800

__global__ __launch_bounds__(256, 1)
void flash_hmma_kernel(const __nv_bfloat16* __restrict__ qhi, const __nv_bfloat16* __restrict__ qlo,
                       const __nv_bfloat16* __restrict__ khi, const __nv_bfloat16* __restrict__ klo,
                       const __nv_bfloat16* __restrict__ vthi, const __nv_bfloat16* __restrict__ vtlo,
                       __half* __restrict__ aoh)
{
    extern __shared__ char smem[];
    uint32_t sbase = smem_u32(smem);
    int tid = threadIdx.x, lane = tid & 31, w = tid >> 5;
    int bh = blockIdx.y;
    int qi = gridDim.x - 1 - blockIdx.x;   // heavy tiles first
    int qrow0 = qi * 128;

    const __nv_bfloat16* qh_b = qhi + (size_t)bh * T_SEQ * HDIM;
    const __nv_bfloat16* ql_b = qlo + (size_t)bh * T_SEQ * HDIM;
    const __nv_bfloat16* kh_b = khi + (size_t)bh * T_SEQ * HDIM;
    const __nv_bfloat16* kl_b = klo + (size_t)bh * T_SEQ * HDIM;
    const __nv_bfloat16* vh_b = vthi + (size_t)bh * HDIM * T_SEQ;
    const __nv_bfloat16* vl_b = vtlo + (size_t)bh * HDIM * T_SEQ;

    // Stage Q (128 x 128, hi+lo) into 4 chunks [128][40]
#pragma unroll
    for (int i = 0; i < 8; i++) {
        int e = tid + i * 256;
        int row = e >> 4, u = e & 15;
        const __nv_bfloat16* gq = qh_b + (size_t)(qrow0 + row) * HDIM + u * 8;
        uint32_t sa = sbase + FS_QH + (u >> 2) * 10240 + (row * 40 + (u & 3) * 8) * 2;
        CP16(sa, gq);
        CP16(sa + (FS_QL - FS_QH), ql_b + (size_t)(qrow0 + row) * HDIM + u * 8);
    }
    CP_COMMIT();

    uint32_t r8 = lane & 7, mi = lane >> 3;
    int tg = lane & 3, g = lane >> 2;
    uint32_t aoff = ((w * 16 + (mi & 1) * 8 + r8) * 40 + (mi >> 1) * 8) * 2;
    uint32_t boff = (((mi >> 1) * 8 + r8) * 40 + (mi & 1) * 8) * 2;

    float oacc[16][4];
#pragma unroll
    for (int i = 0; i < 16; i++)
#pragma unroll
        for (int c = 0; c < 4; c++) oacc[i][c] = 0.f;
    float mrow0 = -1e30f, mrow1 = -1e30f, lrow0 = 0.f, lrow1 = 0.f;

    int row0l = w * 16 + g;                // local row (0..127)
    int gr0 = qrow0 + row0l, gr1 = gr0 + 8;
    int jmax = 2 * qi + 1;

    for (int j = 0; j <= jmax; j++) {
        // load K tile (64x128 hi/lo) and V^T tile (128x64 hi/lo)
#pragma unroll
        for (int i = 0; i < 4; i++) {
            int e = tid + i * 256;
            int row = e >> 4, u = e & 15;
            uint32_t sa = sbase + FS_KH + (u >> 2) * 5120 + (row * 40 + (u & 3) * 8) * 2;
            size_t go = (size_t)(j * 64 + row) * HDIM + u * 8;
            CP16(sa, kh_b + go);
            CP16(sa + (FS_KL - FS_KH), kl_b + go);
        }
#pragma unroll
        for (int i = 0; i < 4; i++) {
            int e = tid + i * 256;
            int d = e >> 3, u = e & 7;
            uint32_t sa = sbase + FS_VH + (u >> 2) * 10240 + (d * 40 + (u & 3) * 8) * 2;
            size_t go = (size_t)d * T_SEQ + j * 64 + u * 8;
            CP16(sa, vh_b + go);
            CP16(sa + (FS_VL - FS_VH), vl_b + go);
        }
        CP_COMMIT(); CP_WAIT0();
        __syncthreads();

        // S = Q K^T (64 cols per warp, 16 rows)
        float sacc[8][4];
#pragma unroll
        for (int i = 0; i < 8; i++)
#pragma unroll
            for (int c = 0; c < 4; c++) sacc[i][c] = 0.f;

#pragma unroll
        for (int ks = 0; ks < 8; ks++) {
            uint32_t ko = (ks & 1) * 32;
            uint32_t qh4[4], ql4[4];
            LDM4(qh4, sbase + FS_QH + (ks >> 1) * 10240 + aoff + ko);
            LDM4(ql4, sbase + FS_QL + (ks >> 1) * 10240 + aoff + ko);
#pragma unroll
            for (int nb = 0; nb < 4; nb++) {
                uint32_t kh4[4], kl4[4];
                LDM4(kh4, sbase + FS_KH + (ks >> 1) * 5120 + boff + nb * 1280 + ko);
                LDM4(kl4, sbase + FS_KL + (ks >> 1) * 5120 + boff + nb * 1280 + ko);
                MMA_BF16(sacc[nb * 2],     qh4, kh4[0], kh4[1]);
                MMA_BF16(sacc[nb * 2],     ql4, kh4[0], kh4[1]);
                MMA_BF16(sacc[nb * 2],     qh4, kl4[0], kl4[1]);
                MMA_BF16(sacc[nb * 2 + 1], qh4, kh4[2], kh4[3]);
                MMA_BF16(sacc[nb * 2 + 1], ql4, kh4[2], kh4[3]);
                MMA_BF16(sacc[nb * 2 + 1], qh4, kl4[2], kl4[3]);
            }
        }

        // causal mask (only the two diagonal tiles need it)
        if (j >= 2 * qi) {
#pragma unroll
            for (int na = 0; na < 8; na++) {
                int gc = j * 64 + na * 8 + tg * 2;
                if (gc     > gr0) sacc[na][0] = -1e30f;
                if (gc + 1 > gr0) sacc[na][1] = -1e30f;
                if (gc     > gr1) sacc[na][2] = -1e30f;
                if (gc + 1 > gr1) sacc[na][3] = -1e30f;
            }
        }

        // online softmax (rows gr0, gr1); reduce over 4-lane tg group
        float m0 = -1e30f, m1 = -1e30f;
#pragma unroll
        for (int na = 0; na < 8; na++) {
            m0 = fmaxf(m0, fmaxf(sacc[na][0], sacc[na][1]));
            m1 = fmaxf(m1, fmaxf(sacc[na][2], sacc[na][3]));
        }
        m0 = fmaxf(m0, __shfl_xor_sync(0xffffffffu, m0, 1));
        m0 = fmaxf(m0, __shfl_xor_sync(0xffffffffu, m0, 2));
        m1 = fmaxf(m1, __shfl_xor_sync(0xffffffffu, m1, 1));
        m1 = fmaxf(m1, __shfl_xor_sync(0xffffffffu, m1, 2));
        float mn0 = fmaxf(mrow0, m0), mn1 = fmaxf(mrow1, m1);
        float cr0 = __expf(mrow0 - mn0), cr1 = __expf(mrow1 - mn1);
        float s0 = 0.f, s1 = 0.f;
#pragma unroll
        for (int na = 0; na < 8; na++) {
            float p00 = __expf(sacc[na][0] - mn0);
            float p01 = __expf(sacc[na][1] - mn0);
            float p10 = __expf(sacc[na][2] - mn1);
            float p11 = __expf(sacc[na][3] - mn1);
            s0 += p00 + p01; s1 += p10 + p11;
            // split-store P to smem (chunked [128][40], warp-private rows)
            char* baseh = smem + FS_PH + (na >> 2) * 10240;
            char* basel = smem + FS_PL + (na >> 2) * 10240;
            uint32_t cw = (na & 3) * 8 + tg * 2;
            split_store2((__nv_bfloat16*)(baseh + (row0l * 40 + cw) * 2),
                         (__nv_bfloat16*)(basel + (row0l * 40 + cw) * 2), p00, p01);
            split_store2((__nv_bfloat16*)(baseh + ((row0l + 8) * 40 + cw) * 2),
                         (__nv_bfloat16*)(basel + ((row0l + 8) * 40 + cw) * 2), p10, p11);
        }
        s0 += __shfl_xor_sync(0xffffffffu, s0, 1);
        s0 += __shfl_xor_sync(0xffffffffu, s0, 2);
        s1 += __shfl_xor_sync(0xffffffffu, s1, 1);
        s1 += __shfl_xor_sync(0xffffffffu, s1, 2);
        lrow0 = lrow0 * cr0 + s0;  lrow1 = lrow1 * cr1 + s1;
        mrow0 = mn0;               mrow1 = mn1;
#pragma unroll
        for (int na = 0; na < 16; na++) {
            oacc[na][0] *= cr0; oacc[na][1] *= cr0;
            oacc[na][2] *= cr1; oacc[na][3] *= cr1;
        }
        __syncwarp();

        // O += P V  (A = P rows of this warp; B = V^T, n = d 128)
#pragma unroll
        for (int kvs = 0; kvs < 4; kvs++) {
            uint32_t ko = (kvs & 1) * 32;
            uint32_t ph4[4], pl4[4];
            LDM4(ph4, sbase + FS_PH + (kvs >> 1) * 10240 + aoff + ko);
            LDM4(pl4, sbase + FS_PL + (kvs >> 1) * 10240 + aoff + ko);
#pragma unroll
            for (int nb = 0; nb < 8; nb++) {
                uint32_t vh4[4], vl4[4];
                LDM4(vh4, sbase + FS_VH + (kvs >> 1) * 10240 + boff + nb * 1280 + ko);
                LDM4(vl4, sbase + FS_VL + (kvs >> 1) * 10240 + boff + nb * 1280 + ko);
                MMA_BF16(oacc[nb * 2],     ph4, vh4[0], vh4[1]);
                MMA_BF16(oacc[nb * 2],     pl4, vh4[0], vh4[1]);
                MMA_BF16(oacc[nb * 2],     ph4, vl4[0], vl4[1]);
                MMA_BF16(oacc[nb * 2 + 1], ph4, vh4[2], vh4[3]);
                MMA_BF16(oacc[nb * 2 + 1], pl4, vh4[2], vh4[3]);
                MMA_BF16(oacc[nb * 2 + 1], ph4, vl4[2], vl4[3]);
            }
        }
        __syncthreads();   // all warps done with K/V before next-tile loads
    }

    // epilogue: normalize, convert fp16, store into Wo's A layout [m][h*128+d]
    int bb = bh >> 4, hh = bh & 15;
    float inv0 = 1.f / lrow0, inv1 = 1.f / lrow1;
    size_t m0i = (size_t)(bb * T_SEQ + gr0) * HID + hh * HDIM;
    size_t m1i = (size_t)(bb * T_SEQ + gr1) * HID + hh * HDIM;
#pragma unroll
    for (int na = 0; na < 16; na++) {
        int col = na * 8 + tg * 2;
        *(__half2*)&aoh[m0i + col] = __floats2half2_rn(oacc[na][0] * inv0, oacc[na][1] * inv0);
        *(__half2*)&aoh[m1i + col] = __floats2half2_rn(oacc[na][2] * inv1, oacc[na][3] * inv1);
    }
}

// ---------------------------------------------------------------------------
// Output projection on mma.sync: out[m, n] row-major fp32.
// ---------------------------------------------------------------------------
__global__ __launch_bounds__(256, 1)
void wo_mma_kernel(const __half* __restrict__ ah,
                   const __half* __restrict__ wh, const __half* __restrict__ wl,
                   float* __restrict__ out)
{
    extern __shared__ char smem[];
    uint32_t sbase = smem_u32(smem);
    int tid = threadIdx.x;
    int n0 = blockIdx.x * 128, m0 = blockIdx.y * 128;

    const __half* Ah = ah + (size_t)m0 * KDIM;
    const __half* Bh = wh + (size_t)3 * HID * KDIM + (size_t)n0 * KDIM;
    const __half* Bl = wl + (size_t)3 * HID * KDIM + (size_t)n0 * KDIM;

    float acc[4][4][4];
#pragma unroll
    for (int i = 0; i < 4; i++)
#pragma unroll
        for (int j = 0; j < 4; j++)
#pragma unroll
            for (int c = 0; c < 4; c++) acc[i][j][c] = 0.f;

    mma_gemm_tile(Ah, Bh, Bl, sbase, acc);

    float* Cs = (float*)smem;
    acc_to_smem(Cs, acc);
    __syncthreads();

    int r = tid >> 1, half = tid & 1;
    float* outp = out + (size_t)(m0 + r) * HID + n0 + half * 64;
#pragma unroll
    for (int j = 0; j < 64; j += 4)
        *(float4*)&outp[j] = *(float4*)&Cs[r * 132 + half * 64 + j];
}

// ---------------------------------------------------------------------------
extern "C" void kernel_launch(void* const* d_in, const int* in_sizes, int n_in,
                              void* d_out, int out_size)
{
    const float* x    = (const float*)d_in[0];
    const float* cosb = (const float*)d_in[1];
    const float* sinb = (const float*)d_in[2];
    const float* Wq   = (const float*)d_in[3];
    const float* Wk   = (const float*)d_in[4];
    const float* Wv   = (const float*)d_in[5];
    const float* Wo   = (const float*)d_in[6];
    float* out = (float*)d_out;

    __half *xh, *wh, *wl;
    __nv_bfloat16 *qhi, *qlo, *khi, *klo, *vthi, *vtlo;
    cudaGetSymbolAddress((void**)&xh, g_xh);
    cudaGetSymbolAddress((void**)&wh, g_wh);
    cudaGetSymbolAddress((void**)&wl, g_wl);
    cudaGetSymbolAddress((void**)&qhi, g_qhi);
    cudaGetSymbolAddress((void**)&qlo, g_qlo);
    cudaGetSymbolAddress((void**)&khi, g_khi);
    cudaGetSymbolAddress((void**)&klo, g_klo);
    cudaGetSymbolAddress((void**)&vthi, g_vthi);
    cudaGetSymbolAddress((void**)&vtlo, g_vtlo);

    // 1) x -> fp16; weights -> fp16 hi/lo split
    const int XN4 = MROWS * KDIM / 4;
    const int WN4 = HID * KDIM / 4;
    cvt_h_kernel<<<XN4 / 256, 256>>>(x, xh, XN4);
    split_h_kernel<<<WN4 / 256, 256>>>(Wq, wh + 0 * (size_t)HID * KDIM, wl + 0 * (size_t)HID * KDIM, WN4);
    split_h_kernel<<<WN4 / 256, 256>>>(Wk, wh + 1 * (size_t)HID * KDIM, wl + 1 * (size_t)HID * KDIM, WN4);
    split_h_kernel<<<WN4 / 256, 256>>>(Wv, wh + 2 * (size_t)HID * KDIM, wl + 2 * (size_t)HID * KDIM, WN4);
    split_h_kernel<<<WN4 / 256, 256>>>(Wo, wh + 3 * (size_t)HID * KDIM, wl + 3 * (size_t)HID * KDIM, WN4);

    // 2) QKV projection + RoPE + layout/split fusion (flash buffers stay bf16)
    cudaFuncSetAttribute(qkv_mma_kernel, cudaFuncAttributeMaxDynamicSharedMemorySize, GEMM_SMEM);
    qkv_mma_kernel<<<dim3(HID / 128, MROWS / 128, 3), 256, GEMM_SMEM>>>(
        xh, wh, wl, cosb, sinb);

    // 3) flash attention (bf16 3-product HMMA); output -> g_xh (fp16, reused)
    cudaFuncSetAttribute(flash_hmma_kernel, cudaFuncAttributeMaxDynamicSharedMemorySize, FLASH_SMEM);
    flash_hmma_kernel<<<dim3(T_SEQ / 128, BATCH * NHEAD), 256, FLASH_SMEM>>>(
        qhi, qlo, khi, klo, vthi, vtlo, xh);

    // 4) output projection (fp16 2-product)
    cudaFuncSetAttribute(wo_mma_kernel, cudaFuncAttributeMaxDynamicSharedMemorySize, GEMM_SMEM);
    wo_mma_kernel<<<dim3(HID / 128, MROWS / 128), 256, GEMM_SMEM>>>(xh, wh, wl, out);
}

// round 12
// speedup vs baseline: 2.6619x; 1.0906x over previous
#include <cuda_runtime.h>
#include <cuda_bf16.h>
#include <cuda_fp16.h>
#include <cstdint>
#include <math.h>

// Problem constants
#define BATCH 2
#define T_SEQ 2048
#define HID   2048
#define NHEAD 16
#define HDIM  128
#define MROWS (BATCH * T_SEQ)   // 4096
#define KDIM  2048
#define NELEM (BATCH * NHEAD * T_SEQ * HDIM)   // 8M

// ---------------------------------------------------------------------------
// Scratch (device globals; allocation-free kernel_launch)
// ---------------------------------------------------------------------------
__device__ __half g_xh[MROWS * KDIM];           // x fp16; later reused as ao fp16
__device__ __half g_wh[4 * HID * KDIM];         // Wq,Wk,Wv,Wo hi (fp16)
__device__ __half g_wl[4 * HID * KDIM];         // residual lo (fp16)
__device__ __half g_qh16[NELEM];                // [b,h][t][d], pre-scaled+RoPE, single fp16
__device__ __half g_kh16[NELEM];                // [b,h][t][d], RoPE, fp16 hi
__device__ __half g_kl16[NELEM];                // fp16 lo
__device__ __half g_vth16[NELEM];               // [b,h][d][t] transposed, fp16 hi
__device__ __half g_vtl16[NELEM];               // fp16 lo

// ---------------------------------------------------------------------------
// PTX helpers (baseline PTX only)
// ---------------------------------------------------------------------------
__device__ __forceinline__ uint32_t smem_u32(const void* p) {
    uint32_t a;
    asm("{ .reg .u64 t; cvta.to.shared.u64 t, %1; cvt.u32.u64 %0, t; }" : "=r"(a) : "l"(p));
    return a;
}
#define LDM4(r, addr) \
    asm volatile("ldmatrix.sync.aligned.m8n8.x4.shared.b16 {%0,%1,%2,%3}, [%4];" \
        : "=r"((r)[0]), "=r"((r)[1]), "=r"((r)[2]), "=r"((r)[3]) : "r"(addr))
#define MMA_F16(d, a, b0, b1) \
    asm volatile("mma.sync.aligned.m16n8k16.row.col.f32.f16.f16.f32 " \
        "{%0,%1,%2,%3}, {%4,%5,%6,%7}, {%8,%9}, {%0,%1,%2,%3};" \
        : "+f"((d)[0]), "+f"((d)[1]), "+f"((d)[2]), "+f"((d)[3]) \
        : "r"((a)[0]), "r"((a)[1]), "r"((a)[2]), "r"((a)[3]), "r"(b0), "r"(b1))
#define CP16(s, g) \
    asm volatile("cp.async.cg.shared.global [%0], [%1], 16;" \
        :: "r"(s), "l"(__cvta_generic_to_global(g)) : "memory")
#define CP_COMMIT() asm volatile("cp.async.commit_group;" ::: "memory")
#define CP_WAIT1()  asm volatile("cp.async.wait_group 1;" ::: "memory")
#define CP_WAIT0()  asm volatile("cp.async.wait_group 0;" ::: "memory")

__device__ __forceinline__ void split_store2h(__half* dh, __half* dl, float a, float b) {
    __half ha = __float2half(a), hb = __float2half(b);
    *(__half2*)dh = __halves2half2(ha, hb);
    *(__half2*)dl = __floats2half2_rn(a - __half2float(ha), b - __half2float(hb));
}

// ---------------------------------------------------------------------------
// fp32 -> fp16 hi (+ optional lo residual) conversion kernels
// ---------------------------------------------------------------------------
struct alignas(8) h2x2 { __half2 a, b; };

__global__ void cvt_h_kernel(const float* __restrict__ src,
                             __half* __restrict__ hi, int n4)
{
    int i = blockIdx.x * blockDim.x + threadIdx.x;
    if (i >= n4) return;
    float4 v = ((const float4*)src)[i];
    h2x2 hv;
    hv.a = __floats2half2_rn(v.x, v.y);
    hv.b = __floats2half2_rn(v.z, v.w);
    ((h2x2*)hi)[i] = hv;
}

__global__ void split_h_kernel(const float* __restrict__ src,
                               __half* __restrict__ hi,
                               __half* __restrict__ lo, int n4)
{
    int i = blockIdx.x * blockDim.x + threadIdx.x;
    if (i >= n4) return;
    float4 v = ((const float4*)src)[i];
    __half h0 = __float2half(v.x), h1 = __float2half(v.y);
    __half h2 = __float2half(v.z), h3 = __float2half(v.w);
    h2x2 hv, lv;
    hv.a = __half2(h0, h1); hv.b = __half2(h2, h3);
    lv.a = __floats2half2_rn(v.x - __half2float(h0), v.y - __half2float(h1));
    lv.b = __floats2half2_rn(v.z - __half2float(h2), v.w - __half2float(h3));
    ((h2x2*)hi)[i] = hv;
    ((h2x2*)lo)[i] = lv;
}

// ---------------------------------------------------------------------------
// mma.sync fp16 2-product GEMM tile: C[128,128] = A[128,K] * B[128,K]^T
// (fp32 acc). C = A*(Bhi+Blo); A single fp16, B split fp16 hi+lo.
// 8 warps = 2(M) x 4(N); warp tile 64x32; BK=32; 3-stage cp.async ring,
// one __syncthreads per chunk. smem: 3 stages x 3 tiles x 10240 B.
// ---------------------------------------------------------------------------
#define TILE_B    10240           // 128 * 40 * 2
#define STAGE_B   (3 * TILE_B)    // 30720
#define GEMM_SMEM (3 * STAGE_B)   // 92160

__device__ __forceinline__ void mma_gemm_tile(
    const __half* __restrict__ Ah,
    const __half* __restrict__ Bh, const __half* __restrict__ Bl,
    uint32_t sbase, float acc[4][4][4])
{
    int tid = threadIdx.x, lane = tid & 31, w = tid >> 5;
    int wm = w & 1, wn = w >> 1;
    uint32_t r8 = lane & 7, mi = lane >> 3;
    uint32_t a_off = ((wm * 64 + ((mi & 1) << 3) + r8) * 40 + ((mi >> 1) << 3)) * 2;
    uint32_t b_off = ((wn * 32 + ((mi >> 1) << 3) + r8) * 40 + ((mi & 1) << 3)) * 2;

    int e0 = tid, e1 = tid + 256;
    int r0 = e0 >> 2, kq0 = e0 & 3;
    int r1 = e1 >> 2, kq1 = e1 & 3;
    uint32_t so0 = (uint32_t)((r0 * 40 + kq0 * 8) * 2);
    uint32_t so1 = (uint32_t)((r1 * 40 + kq1 * 8) * 2);

    auto issue = [&](int c, int buf) {
        uint32_t sb = sbase + buf * STAGE_B;
        size_t gg0 = (size_t)r0 * KDIM + c * 32 + kq0 * 8;
        size_t gg1 = (size_t)r1 * KDIM + c * 32 + kq1 * 8;
        CP16(sb + 0 * TILE_B + so0, Ah + gg0);
        CP16(sb + 0 * TILE_B + so1, Ah + gg1);
        CP16(sb + 1 * TILE_B + so0, Bh + gg0);
        CP16(sb + 1 * TILE_B + so1, Bh + gg1);
        CP16(sb + 2 * TILE_B + so0, Bl + gg0);
        CP16(sb + 2 * TILE_B + so1, Bl + gg1);
    };

    auto compute = [&](int buf) {
        uint32_t sb = sbase + buf * STAGE_B;
#pragma unroll
        for (int ks = 0; ks < 2; ks++) {
            uint32_t k0b = ks * 32;
            uint32_t bh[8], bl[8];
#pragma unroll
            for (int p = 0; p < 2; p++) {
                LDM4(&bh[p * 4], sb + 1 * TILE_B + b_off + p * 1280 + k0b);
                LDM4(&bl[p * 4], sb + 2 * TILE_B + b_off + p * 1280 + k0b);
            }
#pragma unroll
            for (int ma = 0; ma < 4; ma++) {
                uint32_t ah[4];
                LDM4(ah, sb + 0 * TILE_B + a_off + ma * 1280 + k0b);
#pragma unroll
                for (int na = 0; na < 4; na++) {
                    int bi = (na >> 1) * 4 + (na & 1) * 2;
                    MMA_F16(acc[ma][na], ah, bh[bi], bh[bi + 1]);
                    MMA_F16(acc[ma][na], ah, bl[bi], bl[bi + 1]);
                }
            }
        }
    };

    const int NCH = KDIM / 32;   // 64
    issue(0, 0); CP_COMMIT();
    issue(1, 1); CP_COMMIT();
    for (int c = 0; c < NCH; c++) {
        if (c == NCH - 1) { CP_WAIT0(); } else { CP_WAIT1(); }
        __syncthreads();
        if (c + 2 < NCH) { issue(c + 2, (c + 2) % 3); CP_COMMIT(); }
        compute(c % 3);
    }
    __syncthreads();   // protect smem reuse by caller epilogue
}

// stage acc -> smem float[128][132]
__device__ __forceinline__ void acc_to_smem(float* Cs, float acc[4][4][4])
{
    int tid = threadIdx.x, lane = tid & 31, w = tid >> 5;
    int wm = w & 1, wn = w >> 1;
    int g = lane >> 2, tg = lane & 3;
#pragma unroll
    for (int ma = 0; ma < 4; ma++)
#pragma unroll
        for (int na = 0; na < 4; na++) {
            int col = wn * 32 + na * 8 + tg * 2;
            int row = wm * 64 + ma * 16 + g;
            *(float2*)&Cs[row * 132 + col]       = make_float2(acc[ma][na][0], acc[ma][na][1]);
            *(float2*)&Cs[(row + 8) * 132 + col] = make_float2(acc[ma][na][2], acc[ma][na][3]);
        }
}

// ---------------------------------------------------------------------------
// QKV projection: GEMM + RoPE(+scale) + fp16 stores in flash layouts.
// grid (16, 32, 3): n-block = head, m-block = 128 tokens, z = Q/K/V.
// ---------------------------------------------------------------------------
__global__ __launch_bounds__(256, 1)
void qkv_mma_kernel(const __half* __restrict__ xh,
                    const __half* __restrict__ wh, const __half* __restrict__ wl,
                    const float* __restrict__ cosb, const float* __restrict__ sinb)
{
    extern __shared__ char smem[];
    uint32_t sbase = smem_u32(smem);
    int tid = threadIdx.x;
    int z = blockIdx.z;
    int n0 = blockIdx.x * 128, m0 = blockIdx.y * 128;
    int h = n0 >> 7;
    int b = m0 >> 11, t0 = m0 & 2047;
    int bh = b * NHEAD + h;

    const __half* Ah = xh + (size_t)m0 * KDIM;
    const __half* Bh = wh + (size_t)z * HID * KDIM + (size_t)n0 * KDIM;
    const __half* Bl = wl + (size_t)z * HID * KDIM + (size_t)n0 * KDIM;

    float acc[4][4][4];
#pragma unroll
    for (int i = 0; i < 4; i++)
#pragma unroll
        for (int j = 0; j < 4; j++)
#pragma unroll
            for (int c = 0; c < 4; c++) acc[i][j][c] = 0.f;

    mma_gemm_tile(Ah, Bh, Bl, sbase, acc);

    float* Cs = (float*)smem;
    acc_to_smem(Cs, acc);
    __syncthreads();

    if (z < 2) {
        // RoPE (+scale for Q); Q single fp16, K split fp16; store [bh][t][d]
        const float qscale = (z == 0) ? 0.08838834764831845f : 1.0f;
        int r = tid >> 1, half = tid & 1;
        int t = t0 + r;
        int d0 = half * 32;
        size_t rowoff = ((size_t)bh * T_SEQ + t0 + r) * HDIM;
#pragma unroll
        for (int j = 0; j < 32; j += 2) {
            int d = d0 + j;
            float a0 = Cs[r * 132 + d],      a1 = Cs[r * 132 + d + 1];
            float b0 = Cs[r * 132 + d + 64], b1 = Cs[r * 132 + d + 65];
            float c00 = cosb[t * HDIM + d],      s00 = sinb[t * HDIM + d];
            float c01 = cosb[t * HDIM + d + 1],  s01 = sinb[t * HDIM + d + 1];
            float c10 = cosb[t * HDIM + 64 + d],     s10 = sinb[t * HDIM + 64 + d];
            float c11 = cosb[t * HDIM + 64 + d + 1], s11 = sinb[t * HDIM + 64 + d + 1];
            float o00 = (a0 * c00 - b0 * s00) * qscale;
            float o01 = (a1 * c01 - b1 * s01) * qscale;
            float o10 = (b0 * c10 + a0 * s10) * qscale;
            float o11 = (b1 * c11 + a1 * s11) * qscale;
            if (z == 0) {
                *(__half2*)&g_qh16[rowoff + d]      = __floats2half2_rn(o00, o01);
                *(__half2*)&g_qh16[rowoff + 64 + d] = __floats2half2_rn(o10, o11);
            } else {
                split_store2h(&g_kh16[rowoff + d],      &g_kl16[rowoff + d],      o00, o01);
                split_store2h(&g_kh16[rowoff + 64 + d], &g_kl16[rowoff + 64 + d], o10, o11);
            }
        }
    } else {
        // V transpose: store [bh][d][t] split fp16
        __half* dh = g_vth16 + (size_t)bh * HDIM * T_SEQ;
        __half* dl = g_vtl16 + (size_t)bh * HDIM * T_SEQ;
#pragma unroll 4
        for (int i = 0; i < 64; i++) {
            int d = (i & 31) * 4 + (tid >> 6);
            int tl = (i >> 5) * 64 + (tid & 63);
            float val = Cs[tl * 132 + d];
            __half hv = __float2half(val);
            __half lv = __float2half(val - __half2float(hv));
            dh[(size_t)d * T_SEQ + t0 + tl] = hv;
            dl[(size_t)d * T_SEQ + t0 + tl] = lv;
        }
    }
}

// ---------------------------------------------------------------------------
// Flash attention on mma.sync, fp16 2-product, causal. Br=128, Bc=64, D=128.
// 256 threads, 8 warps; warp w owns rows w*16..w*16+15 for the FULL 64 kv cols.
// K/V DOUBLE-buffered (loads overlap compute). Q single fp16, K/V split fp16,
// P single fp16. Output fp16 into aoh [m][h*128+d] (= Wo GEMM A layout).
// ---------------------------------------------------------------------------
#define FS_Q      0               // 40960: 4 chunks [128][40] fp16
#define FS_STAGE  40960           // 2 stages x 81920 (KH,KL,VH,VL @ +0/+20480/+40960/+61440)
#define FS_P      204800          // 20480: 2 chunks [128][40] fp16
#define FLASH_SMEM 225280

__global__ __launch_bounds__(256, 1)
void flash_hmma_kernel(const __half* __restrict__ qh, const __half* __restrict__ khi,
                       const __half* __restrict__ klo, const __half* __restrict__ vthi,
                       const __half* __restrict__ vtlo, __half* __restrict__ aoh)
{
    extern __shared__ char smem[];
    uint32_t sbase = smem_u32(smem);
    int tid = threadIdx.x, lane = tid & 31, w = tid >> 5;
    int bh = blockIdx.y;
    int qi = gridDim.x - 1 - blockIdx.x;   // heavy tiles first
    int qrow0 = qi * 128;

    const __half* qh_b = qh   + (size_t)bh * T_SEQ * HDIM;
    const __half* kh_b = khi  + (size_t)bh * T_SEQ * HDIM;
    const __half* kl_b = klo  + (size_t)bh * T_SEQ * HDIM;
    const __half* vh_b = vthi + (size_t)bh * HDIM * T_SEQ;
    const __half* vl_b = vtlo + (size_t)bh * HDIM * T_SEQ;

    // Stage Q (128 x 128 fp16) into 4 chunks [128][40]
#pragma unroll
    for (int i = 0; i < 8; i++) {
        int e = tid + i * 256;
        int row = e >> 4, u = e & 15;
        uint32_t sa = sbase + FS_Q + (u >> 2) * 10240 + (row * 40 + (u & 3) * 8) * 2;
        CP16(sa, qh_b + (size_t)(qrow0 + row) * HDIM + u * 8);
    }
    CP_COMMIT();

    auto load_kv = [&](int j, int st) {
        uint32_t sb = sbase + FS_STAGE + st * 81920;
#pragma unroll
        for (int i = 0; i < 4; i++) {
            int e = tid + i * 256;
            int row = e >> 4, u = e & 15;
            uint32_t sa = sb + (u >> 2) * 5120 + (row * 40 + (u & 3) * 8) * 2;
            size_t go = (size_t)(j * 64 + row) * HDIM + u * 8;
            CP16(sa, kh_b + go);
            CP16(sa + 20480, kl_b + go);
        }
#pragma unroll
        for (int i = 0; i < 4; i++) {
            int e = tid + i * 256;
            int d = e >> 3, u = e & 7;
            uint32_t sa = sb + 40960 + (u >> 2) * 10240 + (d * 40 + (u & 3) * 8) * 2;
            size_t go = (size_t)d * T_SEQ + j * 64 + u * 8;
            CP16(sa, vh_b + go);
            CP16(sa + 20480, vl_b + go);
        }
        CP_COMMIT();
    };

    uint32_t r8 = lane & 7, mi = lane >> 3;
    int tg = lane & 3, g = lane >> 2;
    uint32_t aoff = ((w * 16 + (mi & 1) * 8 + r8) * 40 + (mi >> 1) * 8) * 2;
    uint32_t boff = (((mi >> 1) * 8 + r8) * 40 + (mi & 1) * 8) * 2;

    float oacc[16][4];
#pragma unroll
    for (int i = 0; i < 16; i++)
#pragma unroll
        for (int c = 0; c < 4; c++) oacc[i][c] = 0.f;
    float mrow0 = -1e30f, mrow1 = -1e30f, lrow0 = 0.f, lrow1 = 0.f;

    int row0l = w * 16 + g;
    int gr0 = qrow0 + row0l, gr1 = gr0 + 8;
    int jmax = 2 * qi + 1;

    load_kv(0, 0);

    for (int j = 0; j <= jmax; j++) {
        if (j < jmax) { load_kv(j + 1, (j + 1) & 1); CP_WAIT1(); }
        else          { CP_WAIT0(); }
        __syncthreads();
        uint32_t kb = sbase + FS_STAGE + (j & 1) * 81920;
        uint32_t vb = kb + 40960;

        // S = Q K^T (64 cols per warp, 16 rows), 2-product
        float sacc[8][4];
#pragma unroll
        for (int i = 0; i < 8; i++)
#pragma unroll
            for (int c = 0; c < 4; c++) sacc[i][c] = 0.f;

#pragma unroll
        for (int ks = 0; ks < 8; ks++) {
            uint32_t ko = (ks & 1) * 32;
            uint32_t q4[4];
            LDM4(q4, sbase + FS_Q + (ks >> 1) * 10240 + aoff + ko);
#pragma unroll
            for (int nb = 0; nb < 4; nb++) {
                uint32_t kh4[4], kl4[4];
                LDM4(kh4, kb + (ks >> 1) * 5120 + boff + nb * 1280 + ko);
                LDM4(kl4, kb + 20480 + (ks >> 1) * 5120 + boff + nb * 1280 + ko);
                MMA_F16(sacc[nb * 2],     q4, kh4[0], kh4[1]);
                MMA_F16(sacc[nb * 2],     q4, kl4[0], kl4[1]);
                MMA_F16(sacc[nb * 2 + 1], q4, kh4[2], kh4[3]);
                MMA_F16(sacc[nb * 2 + 1], q4, kl4[2], kl4[3]);
            }
        }

        // causal mask (only the two diagonal tiles need it)
        if (j >= 2 * qi) {
#pragma unroll
            for (int na = 0; na < 8; na++) {
                int gc = j * 64 + na * 8 + tg * 2;
                if (gc     > gr0) sacc[na][0] = -1e30f;
                if (gc + 1 > gr0) sacc[na][1] = -1e30f;
                if (gc     > gr1) sacc[na][2] = -1e30f;
                if (gc + 1 > gr1) sacc[na][3] = -1e30f;
            }
        }

        // online softmax (rows gr0, gr1); reduce over 4-lane tg group
        float m0 = -1e30f, m1 = -1e30f;
#pragma unroll
        for (int na = 0; na < 8; na++) {
            m0 = fmaxf(m0, fmaxf(sacc[na][0], sacc[na][1]));
            m1 = fmaxf(m1, fmaxf(sacc[na][2], sacc[na][3]));
        }
        m0 = fmaxf(m0, __shfl_xor_sync(0xffffffffu, m0, 1));
        m0 = fmaxf(m0, __shfl_xor_sync(0xffffffffu, m0, 2));
        m1 = fmaxf(m1, __shfl_xor_sync(0xffffffffu, m1, 1));
        m1 = fmaxf(m1, __shfl_xor_sync(0xffffffffu, m1, 2));
        float mn0 = fmaxf(mrow0, m0), mn1 = fmaxf(mrow1, m1);
        float cr0 = __expf(mrow0 - mn0), cr1 = __expf(mrow1 - mn1);
        float s0 = 0.f, s1 = 0.f;
#pragma unroll
        for (int na = 0; na < 8; na++) {
            float p00 = __expf(sacc[na][0] - mn0);
            float p01 = __expf(sacc[na][1] - mn0);
            float p10 = __expf(sacc[na][2] - mn1);
            float p11 = __expf(sacc[na][3] - mn1);
            s0 += p00 + p01; s1 += p10 + p11;
            // P single fp16 store (chunked [128][40], warp-private rows)
            char* basep = smem + FS_P + (na >> 2) * 10240;
            uint32_t cw = (na & 3) * 8 + tg * 2;
            *(__half2*)(basep + (row0l * 40 + cw) * 2)       = __floats2half2_rn(p00, p01);
            *(__half2*)(basep + ((row0l + 8) * 40 + cw) * 2) = __floats2half2_rn(p10, p11);
        }
        s0 += __shfl_xor_sync(0xffffffffu, s0, 1);
        s0 += __shfl_xor_sync(0xffffffffu, s0, 2);
        s1 += __shfl_xor_sync(0xffffffffu, s1, 1);
        s1 += __shfl_xor_sync(0xffffffffu, s1, 2);
        lrow0 = lrow0 * cr0 + s0;  lrow1 = lrow1 * cr1 + s1;
        mrow0 = mn0;               mrow1 = mn1;
#pragma unroll
        for (int na = 0; na < 16; na++) {
            oacc[na][0] *= cr0; oacc[na][1] *= cr0;
            oacc[na][2] *= cr1; oacc[na][3] *= cr1;
        }
        __syncwarp();

        // O += P V  (A = P rows of this warp; B = V^T, n = d 128), 2-product
#pragma unroll
        for (int kvs = 0; kvs < 4; kvs++) {
            uint32_t ko = (kvs & 1) * 32;
            uint32_t p4[4];
            LDM4(p4, sbase + FS_P + (kvs >> 1) * 10240 + aoff + ko);
#pragma unroll
            for (int nb = 0; nb < 8; nb++) {
                uint32_t vh4[4], vl4[4];
                LDM4(vh4, vb + (kvs >> 1) * 10240 + boff + nb * 1280 + ko);
                LDM4(vl4, vb + 20480 + (kvs >> 1) * 10240 + boff + nb * 1280 + ko);
                MMA_F16(oacc[nb * 2],     p4, vh4[0], vh4[1]);
                MMA_F16(oacc[nb * 2],     p4, vl4[0], vl4[1]);
                MMA_F16(oacc[nb * 2 + 1], p4, vh4[2], vh4[3]);
                MMA_F16(oacc[nb * 2 + 1], p4, vl4[2], vl4[3]);
            }
        }
        __syncthreads();   // all warps done with this stage before overwrite at j+2
    }

    // epilogue: normalize, convert fp16, store into Wo's A layout [m][h*128+d]
    int bb = bh >> 4, hh = bh & 15;
    float inv0 = 1.f / lrow0, inv1 = 1.f / lrow1;
    size_t m0i = (size_t)(bb * T_SEQ + gr0) * HID + hh * HDIM;
    size_t m1i = (size_t)(bb * T_SEQ + gr1) * HID + hh * HDIM;
#pragma unroll
    for (int na = 0; na < 16; na++) {
        int col = na * 8 + tg * 2;
        *(__half2*)&aoh[m0i + col] = __floats2half2_rn(oacc[na][0] * inv0, oacc[na][1] * inv0);
        *(__half2*)&aoh[m1i + col] = __floats2half2_rn(oacc[na][2] * inv1, oacc[na][3] * inv1);
    }
}

// ---------------------------------------------------------------------------
// Output projection on mma.sync: out[m, n] row-major fp32.
// ---------------------------------------------------------------------------
__global__ __launch_bounds__(256, 1)
void wo_mma_kernel(const __half* __restrict__ ah,
                   const __half* __restrict__ wh, const __half* __restrict__ wl,
                   float* __restrict__ out)
{
    extern __shared__ char smem[];
    uint32_t sbase = smem_u32(smem);
    int tid = threadIdx.x;
    int n0 = blockIdx.x * 128, m0 = blockIdx.y * 128;

    const __half* Ah = ah + (size_t)m0 * KDIM;
    const __half* Bh = wh + (size_t)3 * HID * KDIM + (size_t)n0 * KDIM;
    const __half* Bl = wl + (size_t)3 * HID * KDIM + (size_t)n0 * KDIM;

    float acc[4][4][4];
#pragma unroll
    for (int i = 0; i < 4; i++)
#pragma unroll
        for (int j = 0; j < 4; j++)
#pragma unroll
            for (int c = 0; c < 4; c++) acc[i][j][c] = 0.f;

    mma_gemm_tile(Ah, Bh, Bl, sbase, acc);

    float* Cs = (float*)smem;
    acc_to_smem(Cs, acc);
    __syncthreads();

    int r = tid >> 1, half = tid & 1;
    float* outp = out + (size_t)(m0 + r) * HID + n0 + half * 64;
#pragma unroll
    for (int j = 0; j < 64; j += 4)
        *(float4*)&outp[j] = *(float4*)&Cs[r * 132 + half * 64 + j];
}

// ---------------------------------------------------------------------------
extern "C" void kernel_launch(void* const* d_in, const int* in_sizes, int n_in,
                              void* d_out, int out_size)
{
    const float* x    = (const float*)d_in[0];
    const float* cosb = (const float*)d_in[1];
    const float* sinb = (const float*)d_in[2];
    const float* Wq   = (const float*)d_in[3];
    const float* Wk   = (const float*)d_in[4];
    const float* Wv   = (const float*)d_in[5];
    const float* Wo   = (const float*)d_in[6];
    float* out = (float*)d_out;

    __half *xh, *wh, *wl, *qh, *kh, *kl, *vth, *vtl;
    cudaGetSymbolAddress((void**)&xh,  g_xh);
    cudaGetSymbolAddress((void**)&wh,  g_wh);
    cudaGetSymbolAddress((void**)&wl,  g_wl);
    cudaGetSymbolAddress((void**)&qh,  g_qh16);
    cudaGetSymbolAddress((void**)&kh,  g_kh16);
    cudaGetSymbolAddress((void**)&kl,  g_kl16);
    cudaGetSymbolAddress((void**)&vth, g_vth16);
    cudaGetSymbolAddress((void**)&vtl, g_vtl16);

    // 1) x -> fp16; weights -> fp16 hi/lo split
    const int XN4 = MROWS * KDIM / 4;
    const int WN4 = HID * KDIM / 4;
    cvt_h_kernel<<<XN4 / 256, 256>>>(x, xh, XN4);
    split_h_kernel<<<WN4 / 256, 256>>>(Wq, wh + 0 * (size_t)HID * KDIM, wl + 0 * (size_t)HID * KDIM, WN4);
    split_h_kernel<<<WN4 / 256, 256>>>(Wk, wh + 1 * (size_t)HID * KDIM, wl + 1 * (size_t)HID * KDIM, WN4);
    split_h_kernel<<<WN4 / 256, 256>>>(Wv, wh + 2 * (size_t)HID * KDIM, wl + 2 * (size_t)HID * KDIM, WN4);
    split_h_kernel<<<WN4 / 256, 256>>>(Wo, wh + 3 * (size_t)HID * KDIM, wl + 3 * (size_t)HID * KDIM, WN4);

    // 2) QKV projection + RoPE + layout fusion (fp16 flash buffers)
    cudaFuncSetAttribute(qkv_mma_kernel, cudaFuncAttributeMaxDynamicSharedMemorySize, GEMM_SMEM);
    qkv_mma_kernel<<<dim3(HID / 128, MROWS / 128, 3), 256, GEMM_SMEM>>>(
        xh, wh, wl, cosb, sinb);

    // 3) flash attention (fp16 2-product, double-buffered K/V); out -> g_xh
    cudaFuncSetAttribute(flash_hmma_kernel, cudaFuncAttributeMaxDynamicSharedMemorySize, FLASH_SMEM);
    flash_hmma_kernel<<<dim3(T_SEQ / 128, BATCH * NHEAD), 256, FLASH_SMEM>>>(
        qh, kh, kl, vth, vtl, xh);

    // 4) output projection (fp16 2-product)
    cudaFuncSetAttribute(wo_mma_kernel, cudaFuncAttributeMaxDynamicSharedMemorySize, GEMM_SMEM);
    wo_mma_kernel<<<dim3(HID / 128, MROWS / 128), 256, GEMM_SMEM>>>(xh, wh, wl, out);
}